// round 2
// baseline (speedup 1.0000x reference)
#include <cuda_runtime.h>
#include <cuda_bf16.h>
#include <math.h>
#include <stdint.h>

// ---------------- problem constants ----------------
#define U_NODES 40000
#define I_NODES 30000
#define N_NODES 70000
#define D_LAT   128
#define D_X     64

// ---------------- scratch layout (floats) ----------------
// one big __device__ buffer; offsets all 16B-aligned
static const size_t SZ_TFEAT = (size_t)I_NODES * D_LAT;              // 3,840,000
static const size_t SZ_CNT   = (size_t)I_NODES;                      // 30,000
static const size_t SZ_X     = (size_t)N_NODES * D_LAT;              // 8,960,000
static const size_t SZ_X64   = (size_t)N_NODES * D_X;                // 4,480,000

static const size_t OFF_TFEAT = 0;
static const size_t OFF_CNT   = OFF_TFEAT + SZ_TFEAT;                // 3,840,000
static const size_t OFF_X     = OFF_CNT   + 30000 + 2000;            // pad -> 3,872,000
static const size_t OFF_AGG   = OFF_X     + SZ_X;
static const size_t OFF_H     = OFF_AGG   + SZ_X;
static const size_t OFF_X64   = OFF_H     + SZ_X;
static const size_t OFF_H64   = OFF_X64   + SZ_X64;
static const size_t OFF_REP   = OFF_H64   + SZ_X64;                  // 3 * N*64
static const size_t OFF_MLPT  = OFF_REP   + 3 * SZ_X64;
static const size_t OFF_LIN1T = OFF_MLPT  + 3 * 128 * 128;
static const size_t OFF_G1T   = OFF_LIN1T + 3 * 128 * 64;
static const size_t OFF_LIN2T = OFF_G1T   + 3 * 128 * 64;
static const size_t OFF_G2T   = OFF_LIN2T + 3 * 64 * 64;
static const size_t SCRATCH_TOTAL = OFF_G2T + 3 * 64 * 64;

__device__ float g_scratch[SCRATCH_TOTAL];

// ---------------- helpers ----------------
__device__ __forceinline__ float lrelu(float v) { return v >= 0.0f ? v : 0.01f * v; }

__device__ __forceinline__ void red_add4(float* p, float4 v) {
    asm volatile("red.global.add.v4.f32 [%0], {%1,%2,%3,%4};"
                 :: "l"(p), "f"(v.x), "f"(v.y), "f"(v.z), "f"(v.w) : "memory");
}
__device__ __forceinline__ void red_add2(float* p, float2 v) {
    asm volatile("red.global.add.v2.f32 [%0], {%1,%2};"
                 :: "l"(p), "f"(v.x), "f"(v.y) : "memory");
}

__device__ __forceinline__ float warp_sum(float v) {
#pragma unroll
    for (int o = 16; o > 0; o >>= 1) v += __shfl_xor_sync(0xFFFFFFFFu, v, o);
    return v;
}

// ---------------- small utility kernels ----------------
__global__ void zero_kernel(float4* __restrict__ p, long n4) {
    long i = (long)blockIdx.x * blockDim.x + threadIdx.x;
    if (i < n4) p[i] = make_float4(0.f, 0.f, 0.f, 0.f);
}

// in: (3, R, C)  ->  out: (3, C, R)   (out[m][c][r] = in[m][r][c])
__global__ void transpose_w(const float* __restrict__ in, float* __restrict__ out,
                            int R, int C) {
    int i = blockIdx.x * blockDim.x + threadIdx.x;
    int total = 3 * R * C;
    if (i >= total) return;
    int m = i / (R * C);
    int rem = i - m * R * C;
    int r = rem / C;
    int c = rem - r * C;
    out[m * R * C + c * R + r] = in[i];
}

// words scatter: sums[item] += word_emb[word], cnt[item] += 1   (warp per word)
__global__ void words_scatter(const int* __restrict__ words,
                              const float* __restrict__ word_emb,
                              float* __restrict__ sums, float* __restrict__ cnt, int W) {
    int gw = (int)(((long)blockIdx.x * blockDim.x + threadIdx.x) >> 5);
    int lane = threadIdx.x & 31;
    if (gw >= W) return;
    int item = words[gw];
    int word = words[W + gw];
    float4 v = ((const float4*)(word_emb + (size_t)word * D_LAT))[lane];
    red_add4(sums + (size_t)item * D_LAT + lane * 4, v);
    if (lane == 0) atomicAdd(cnt + item, 1.0f);
}

__global__ void tfeat_div(float* __restrict__ t, const float* __restrict__ cnt) {
    int i = blockIdx.x * blockDim.x + threadIdx.x;
    if (i >= I_NODES * D_LAT) return;
    float c = fmaxf(cnt[i >> 7], 1.0f);
    t[i] = t[i] / c;
}

// build + L2-normalize x rows: row<U reads pref, else reads x (tf already stored)
__global__ void normalize_x(const float* __restrict__ pref_m, float* __restrict__ x) {
    int row = (int)(((long)blockIdx.x * blockDim.x + threadIdx.x) >> 5);
    int lane = threadIdx.x & 31;
    if (row >= N_NODES) return;
    const float* src = (row < U_NODES) ? (pref_m + (size_t)row * D_LAT)
                                       : (x + (size_t)row * D_LAT);
    float4 v = ((const float4*)src)[lane];
    float ss = v.x * v.x + v.y * v.y + v.z * v.z + v.w * v.w;
    ss = warp_sum(ss);
    float s = 1.0f / fmaxf(sqrtf(ss), 1e-12f);
    v.x *= s; v.y *= s; v.z *= s; v.w *= s;
    ((float4*)(x + (size_t)row * D_LAT))[lane] = v;
}

// edge scatter, 128-dim rows: agg[dst] += x[src]   (warp per edge)
__global__ void scatter_edges128(const int* __restrict__ ei, const float* __restrict__ x,
                                 float* __restrict__ agg, int E) {
    int e = (int)(((long)blockIdx.x * blockDim.x + threadIdx.x) >> 5);
    int lane = threadIdx.x & 31;
    if (e >= E) return;
    int s = ei[e];
    int d = ei[E + e];
    float4 v = ((const float4*)(x + (size_t)s * D_LAT))[lane];
    red_add4(agg + (size_t)d * D_LAT + lane * 4, v);
}

// edge scatter, 64-dim rows
__global__ void scatter_edges64(const int* __restrict__ ei, const float* __restrict__ x,
                                float* __restrict__ agg, int E) {
    int e = (int)(((long)blockIdx.x * blockDim.x + threadIdx.x) >> 5);
    int lane = threadIdx.x & 31;
    if (e >= E) return;
    int s = ei[e];
    int d = ei[E + e];
    float2 v = ((const float2*)(x + (size_t)s * D_X))[lane];
    red_add2(agg + (size_t)d * D_X + lane * 2, v);
}

// ---------------- GEMM:  C[M,NOUT] = A[M,K] @ B[K,NOUT] (+bias) (lrelu) ----------------
template <int K, int NOUT, bool BIAS, bool LRELU>
__global__ __launch_bounds__(256) void gemm_kernel(const float* __restrict__ A,
                                                   const float* __restrict__ B,
                                                   const float* __restrict__ bias,
                                                   float* __restrict__ C, int M) {
    const int BM = 64, BK = 32;
    const int CN = NOUT / 32;                 // cols per lane (4 or 2)
    __shared__ float As[BM][BK];
    __shared__ float Bs[BK][NOUT];
    int tid = threadIdx.x;
    int tx = tid & 31, ty = tid >> 5;         // ty 0..7
    int m0 = blockIdx.x * BM;

    float acc[8][CN];
#pragma unroll
    for (int i = 0; i < 8; i++)
#pragma unroll
        for (int c = 0; c < CN; c++) acc[i][c] = 0.0f;

    for (int k0 = 0; k0 < K; k0 += BK) {
        // A tile: 64x32 = 512 float4, 2 per thread
#pragma unroll
        for (int p = 0; p < 2; p++) {
            int idx = tid + p * 256;
            int r = idx >> 3;
            int c4 = idx & 7;
            int gm = m0 + r;
            float4 v = (gm < M) ? *(const float4*)&A[(size_t)gm * K + k0 + c4 * 4]
                                : make_float4(0.f, 0.f, 0.f, 0.f);
            *(float4*)&As[r][c4 * 4] = v;
        }
        // B tile: 32 x NOUT floats = 8*NOUT float4, CN per thread
#pragma unroll
        for (int p = 0; p < CN; p++) {
            int idx = tid + p * 256;
            int r = idx / (NOUT / 4);
            int c4 = idx % (NOUT / 4);
            *(float4*)&Bs[r][c4 * 4] = *(const float4*)&B[(size_t)(k0 + r) * NOUT + c4 * 4];
        }
        __syncthreads();
#pragma unroll
        for (int k = 0; k < BK; k++) {
            float bv[CN];
            if (CN == 4) {
                float4 t = *(const float4*)&Bs[k][tx * 4];
                bv[0] = t.x; bv[1] = t.y; bv[2] = t.z; bv[3] = t.w;
            } else {
                float2 t = *(const float2*)&Bs[k][tx * 2];
                bv[0] = t.x; bv[1] = t.y;
            }
#pragma unroll
            for (int i = 0; i < 8; i++) {
                float a = As[ty * 8 + i][k];
#pragma unroll
                for (int c = 0; c < CN; c++) acc[i][c] += a * bv[c];
            }
        }
        __syncthreads();
    }
#pragma unroll
    for (int i = 0; i < 8; i++) {
        int gm = m0 + ty * 8 + i;
        if (gm < M) {
#pragma unroll
            for (int c = 0; c < CN; c++) {
                int n = tx * CN + c;
                float v = acc[i][c];
                if (BIAS) v += bias[n];
                if (LRELU) v = lrelu(v);
                C[(size_t)gm * NOUT + n] = v;
            }
        }
    }
}

// ---------- dual GEMM:  out = lrelu( A2@B2 + b2 + lrelu(A1@B1 + b1) + id ) ----------
template <int K>
__global__ __launch_bounds__(256) void dual_gemm_kernel(
    const float* __restrict__ A1, const float* __restrict__ B1, const float* __restrict__ b1,
    const float* __restrict__ A2, const float* __restrict__ B2, const float* __restrict__ b2,
    const float* __restrict__ idemb, float* __restrict__ out, int M) {
    const int BM = 64, BK = 32, NOUT = 64;
    __shared__ float As1[BM][BK], As2[BM][BK];
    __shared__ float Bs1[BK][NOUT], Bs2[BK][NOUT];
    int tid = threadIdx.x;
    int tx = tid & 31, ty = tid >> 5;
    int m0 = blockIdx.x * BM;

    float acc1[8][2], acc2[8][2];
#pragma unroll
    for (int i = 0; i < 8; i++) {
        acc1[i][0] = acc1[i][1] = 0.f;
        acc2[i][0] = acc2[i][1] = 0.f;
    }

    for (int k0 = 0; k0 < K; k0 += BK) {
#pragma unroll
        for (int p = 0; p < 2; p++) {
            int idx = tid + p * 256;
            int r = idx >> 3;
            int c4 = idx & 7;
            int gm = m0 + r;
            float4 z = make_float4(0.f, 0.f, 0.f, 0.f);
            float4 va = (gm < M) ? *(const float4*)&A1[(size_t)gm * K + k0 + c4 * 4] : z;
            float4 vb = (gm < M) ? *(const float4*)&A2[(size_t)gm * K + k0 + c4 * 4] : z;
            *(float4*)&As1[r][c4 * 4] = va;
            *(float4*)&As2[r][c4 * 4] = vb;
        }
#pragma unroll
        for (int p = 0; p < 2; p++) {
            int idx = tid + p * 256;
            int r = idx >> 4;      // NOUT/4 = 16 float4 per row
            int c4 = idx & 15;
            *(float4*)&Bs1[r][c4 * 4] = *(const float4*)&B1[(size_t)(k0 + r) * NOUT + c4 * 4];
            *(float4*)&Bs2[r][c4 * 4] = *(const float4*)&B2[(size_t)(k0 + r) * NOUT + c4 * 4];
        }
        __syncthreads();
#pragma unroll
        for (int k = 0; k < BK; k++) {
            float2 bv1 = *(const float2*)&Bs1[k][tx * 2];
            float2 bv2 = *(const float2*)&Bs2[k][tx * 2];
#pragma unroll
            for (int i = 0; i < 8; i++) {
                float a1 = As1[ty * 8 + i][k];
                float a2 = As2[ty * 8 + i][k];
                acc1[i][0] += a1 * bv1.x; acc1[i][1] += a1 * bv1.y;
                acc2[i][0] += a2 * bv2.x; acc2[i][1] += a2 * bv2.y;
            }
        }
        __syncthreads();
    }
#pragma unroll
    for (int i = 0; i < 8; i++) {
        int gm = m0 + ty * 8 + i;
        if (gm < M) {
#pragma unroll
            for (int c = 0; c < 2; c++) {
                int n = tx * 2 + c;
                float v1 = lrelu(acc1[i][c] + b1[n]);
                float v = acc2[i][c] + b2[n] + v1 + idemb[(size_t)gm * D_X + n];
                out[(size_t)gm * D_X + n] = lrelu(v);
            }
        }
    }
}

// ---------------- final scoring ----------------
__global__ void final_kernel(const float* __restrict__ rep,
                             const int* __restrict__ users, const int* __restrict__ pos,
                             const int* __restrict__ neg, float* __restrict__ out, int Bn) {
    int gw = (int)(((long)blockIdx.x * blockDim.x + threadIdx.x) >> 5);
    int lane = threadIdx.x & 31;
    if (gw >= Bn) return;
    int u = users[gw], p = pos[gw], n = neg[gw];
    const size_t stride = (size_t)N_NODES * D_X;
    const float* r0 = rep;
    const float* r1 = rep + stride;
    const float* r2 = rep + 2 * stride;

    auto ld = [&](const float* base, int node) {
        return ((const float2*)(base + (size_t)node * D_X))[lane];
    };
    float2 t_u = ld(r2, u), t_p = ld(r2, p), t_n = ld(r2, n);
    float2 a_u = ld(r0, u), b_u = ld(r1, u);
    float2 a_p = ld(r0, p), b_p = ld(r1, p);
    float2 a_n = ld(r0, n), b_n = ld(r1, n);

    const float third = 1.0f / 3.0f;
    float2 pu = make_float2((a_u.x + b_u.x + t_u.x) * third, (a_u.y + b_u.y + t_u.y) * third);
    float2 pp = make_float2((a_p.x + b_p.x + t_p.x) * third, (a_p.y + b_p.y + t_p.y) * third);
    float2 pn = make_float2((a_n.x + b_n.x + t_n.x) * third, (a_n.y + b_n.y + t_n.y) * third);

    float prep  = t_u.x * t_p.x + t_u.y * t_p.y;
    float pren  = t_u.x * t_n.x + t_u.y * t_n.y;
    float postp = pu.x * pp.x + pu.y * pp.y;
    float postn = pu.x * pn.x + pu.y * pn.y;

    prep = warp_sum(prep);
    pren = warp_sum(pren);
    postp = warp_sum(postp);
    postn = warp_sum(postn);

    if (lane == 0) {
        float sp = 1.0f / (1.0f + expf(-prep));
        float sn = 1.0f / (1.0f + expf(-pren));
        out[gw]          = postp * sp;
        out[Bn + gw]     = postn * sn;
        out[2 * Bn + gw] = prep;
        out[3 * Bn + gw] = pren;
    }
}

// ---------------- host orchestration ----------------
static inline int nblk(long n, int t) { return (int)((n + t - 1) / t); }

extern "C" void kernel_launch(void* const* d_in, const int* in_sizes, int n_in,
                              void* d_out, int out_size) {
    const float* v_feat   = (const float*)d_in[0];
    const float* a_feat   = (const float*)d_in[1];
    const float* word_emb = (const float*)d_in[2];
    const float* id_emb   = (const float*)d_in[3];
    const float* pref     = (const float*)d_in[4];
    const float* mlp_w    = (const float*)d_in[5];
    const float* mlp_b    = (const float*)d_in[6];
    const float* conv1_w  = (const float*)d_in[7];
    const float* lin1_w   = (const float*)d_in[8];
    const float* lin1_b   = (const float*)d_in[9];
    const float* g1_w     = (const float*)d_in[10];
    const float* g1_b     = (const float*)d_in[11];
    const float* conv2_w  = (const float*)d_in[12];
    const float* lin2_w   = (const float*)d_in[13];
    const float* lin2_b   = (const float*)d_in[14];
    const float* g2_w     = (const float*)d_in[15];
    const float* g2_b     = (const float*)d_in[16];
    const int*   edges    = (const int*)d_in[17];
    const int*   words    = (const int*)d_in[18];
    const int*   users    = (const int*)d_in[19];
    const int*   posn     = (const int*)d_in[20];
    const int*   negn     = (const int*)d_in[21];

    const int E  = in_sizes[17] / 2;   // 500000
    const int W  = in_sizes[18] / 2;   // 600000
    const int Bn = in_sizes[19];       // 2048

    float* sc = nullptr;
    cudaGetSymbolAddress((void**)&sc, g_scratch);

    float* tfeat = sc + OFF_TFEAT;
    float* cnt   = sc + OFF_CNT;
    float* x     = sc + OFF_X;
    float* agg   = sc + OFF_AGG;
    float* h     = sc + OFF_H;
    float* x64   = sc + OFF_X64;
    float* h64   = sc + OFF_H64;
    float* rep   = sc + OFF_REP;

    // ---- weight transposes (tiny) ----
    transpose_w<<<nblk(3L * 128 * 128, 256), 256>>>(mlp_w,  sc + OFF_MLPT, 128, 128);
    transpose_w<<<nblk(3L * 64 * 128, 256), 256>>>(lin1_w, sc + OFF_LIN1T, 64, 128);
    transpose_w<<<nblk(3L * 64 * 128, 256), 256>>>(g1_w,   sc + OFF_G1T,   64, 128);
    transpose_w<<<nblk(3L * 64 * 64, 256), 256>>>(lin2_w, sc + OFF_LIN2T, 64, 64);
    transpose_w<<<nblk(3L * 64 * 64, 256), 256>>>(g2_w,   sc + OFF_G2T,   64, 64);

    // ---- t_feat = scatter_mean(word_emb[word_ids], item_ids) ----
    zero_kernel<<<nblk((long)SZ_TFEAT / 4, 256), 256>>>((float4*)tfeat, (long)SZ_TFEAT / 4);
    zero_kernel<<<nblk((long)I_NODES / 4, 256), 256>>>((float4*)cnt, (long)I_NODES / 4);
    words_scatter<<<nblk((long)W * 32, 256), 256>>>(words, word_emb, tfeat, cnt, W);
    tfeat_div<<<nblk((long)I_NODES * D_LAT, 256), 256>>>(tfeat, cnt);

    for (int m = 0; m < 3; m++) {
        const float* feat = (m == 0) ? v_feat : (m == 1) ? a_feat : tfeat;

        // tf = feat @ mlp_w.T + mlp_b   -> x rows [U, N)
        gemm_kernel<128, 128, true, false><<<nblk(I_NODES, 64), 256>>>(
            feat, sc + OFF_MLPT + (size_t)m * 128 * 128, mlp_b + m * 128,
            x + (size_t)U_NODES * D_LAT, I_NODES);

        // x = normalize(concat(pref, tf))
        normalize_x<<<nblk((long)N_NODES * 32, 256), 256>>>(
            pref + (size_t)m * U_NODES * D_LAT, x);

        // agg = segment_sum(x[src] -> dst)
        zero_kernel<<<nblk((long)SZ_X / 4, 256), 256>>>((float4*)agg, (long)SZ_X / 4);
        scatter_edges128<<<nblk((long)E * 32, 256), 256>>>(edges, x, agg, E);

        // h = lrelu(agg @ conv1_w)
        gemm_kernel<128, 128, false, true><<<nblk(N_NODES, 64), 256>>>(
            agg, conv1_w + (size_t)m * 128 * 128, nullptr, h, N_NODES);

        // x64 = lrelu(h@g1.T + g1b + lrelu(x@l1.T + l1b) + id)
        dual_gemm_kernel<128><<<nblk(N_NODES, 64), 256>>>(
            x, sc + OFF_LIN1T + (size_t)m * 128 * 64, lin1_b + m * 64,
            h, sc + OFF_G1T + (size_t)m * 128 * 64, g1_b + m * 64,
            id_emb, x64, N_NODES);

        // layer 2
        zero_kernel<<<nblk((long)SZ_X64 / 4, 256), 256>>>((float4*)agg, (long)SZ_X64 / 4);
        scatter_edges64<<<nblk((long)E * 32, 256), 256>>>(edges, x64, agg, E);

        gemm_kernel<64, 64, false, true><<<nblk(N_NODES, 64), 256>>>(
            agg, conv2_w + (size_t)m * 64 * 64, nullptr, h64, N_NODES);

        dual_gemm_kernel<64><<<nblk(N_NODES, 64), 256>>>(
            x64, sc + OFF_LIN2T + (size_t)m * 64 * 64, lin2_b + m * 64,
            h64, sc + OFF_G2T + (size_t)m * 64 * 64, g2_b + m * 64,
            id_emb, rep + (size_t)m * N_NODES * D_X, N_NODES);
    }

    final_kernel<<<nblk((long)Bn * 32, 256), 256>>>(rep, users, posn, negn,
                                                    (float*)d_out, Bn);
}

// round 3
// speedup vs baseline: 1.1771x; 1.1771x over previous
#include <cuda_runtime.h>
#include <cuda_bf16.h>
#include <math.h>
#include <stdint.h>

// ---------------- problem constants ----------------
#define U_NODES 40000
#define I_NODES 30000
#define N_NODES 70000
#define D_LAT   128
#define D_X     64

// ---------------- scratch layout (floats) ----------------
static const size_t SZ_TFEAT = (size_t)I_NODES * D_LAT;
static const size_t SZ_X     = (size_t)N_NODES * D_LAT;
static const size_t SZ_X64   = (size_t)N_NODES * D_X;

static const size_t OFF_TFEAT = 0;
static const size_t OFF_CNT   = OFF_TFEAT + SZ_TFEAT;
static const size_t OFF_X     = OFF_CNT   + 30000 + 2000;
static const size_t OFF_AGG   = OFF_X     + SZ_X;
static const size_t OFF_H     = OFF_AGG   + SZ_X;
static const size_t OFF_X64   = OFF_H     + SZ_X;
static const size_t OFF_H64   = OFF_X64   + SZ_X64;
static const size_t OFF_REP   = OFF_H64   + SZ_X64;
static const size_t OFF_MLPT  = OFF_REP   + 3 * SZ_X64;
static const size_t OFF_LIN1T = OFF_MLPT  + 3 * 128 * 128;
static const size_t OFF_G1T   = OFF_LIN1T + 3 * 128 * 64;
static const size_t OFF_LIN2T = OFF_G1T   + 3 * 128 * 64;
static const size_t OFF_G2T   = OFF_LIN2T + 3 * 64 * 64;
static const size_t SCRATCH_TOTAL = OFF_G2T + 3 * 64 * 64;

__device__ float g_scratch[SCRATCH_TOTAL];

// ---------------- helpers ----------------
__device__ __forceinline__ float lrelu(float v) { return v >= 0.0f ? v : 0.01f * v; }

__device__ __forceinline__ void red_add4(float* p, float4 v) {
    asm volatile("red.global.add.v4.f32 [%0], {%1,%2,%3,%4};"
                 :: "l"(p), "f"(v.x), "f"(v.y), "f"(v.z), "f"(v.w) : "memory");
}
__device__ __forceinline__ void red_add2(float* p, float2 v) {
    asm volatile("red.global.add.v2.f32 [%0], {%1,%2};"
                 :: "l"(p), "f"(v.x), "f"(v.y) : "memory");
}

__device__ __forceinline__ float warp_sum(float v) {
#pragma unroll
    for (int o = 16; o > 0; o >>= 1) v += __shfl_xor_sync(0xFFFFFFFFu, v, o);
    return v;
}

__device__ __forceinline__ uint32_t f2tf(float f) {
    uint32_t r;
    asm("cvt.rna.tf32.f32 %0, %1;" : "=r"(r) : "f"(f));
    return r;
}

// D += A(16x8,row) * B(8x8,col)  tf32, fp32 accum
__device__ __forceinline__ void mma_tf32(float4& d, const uint32_t* a, const uint32_t* b) {
    asm volatile(
        "mma.sync.aligned.m16n8k8.row.col.f32.tf32.tf32.f32 "
        "{%0,%1,%2,%3}, {%4,%5,%6,%7}, {%8,%9}, {%0,%1,%2,%3};"
        : "+f"(d.x), "+f"(d.y), "+f"(d.z), "+f"(d.w)
        : "r"(a[0]), "r"(a[1]), "r"(a[2]), "r"(a[3]), "r"(b[0]), "r"(b[1]));
}

// ---- smem tile fills (fragment-order layout) ----
// A perm layout: idx = ((k8*(BM/16) + tm)*32 + lane)*4 + reg
//   lane = (m%8)*4 + (k%8)%4 ; reg = (m%16>=8) + 2*((k%8)>=4)
template <int BM, int BK>
__device__ __forceinline__ void fill_A(uint32_t* As, const float* __restrict__ A,
                                       int m0, int M, int lda, int k0) {
    const int NF4 = BM * BK / 4 / 256;
    int tid = threadIdx.x;
#pragma unroll
    for (int p = 0; p < NF4; p++) {
        int f = tid + p * 256;
        int m = f / (BK / 4);
        int k4 = f % (BK / 4);
        int gm = m0 + m;
        float4 v = make_float4(0.f, 0.f, 0.f, 0.f);
        if (gm < M) v = *(const float4*)&A[(size_t)gm * lda + k0 + k4 * 4];
        int k8 = k4 >> 1;
        int tm = m >> 4;
        int lane_base = (m & 7) * 4;
        int reg = (((m & 15) >= 8) ? 1 : 0) + ((k4 & 1) ? 2 : 0);
        uint32_t* dst = As + (size_t)((k8 * (BM / 16) + tm) * 32) * 4 + reg;
        dst[(lane_base + 0) * 4] = f2tf(v.x);
        dst[(lane_base + 1) * 4] = f2tf(v.y);
        dst[(lane_base + 2) * 4] = f2tf(v.z);
        dst[(lane_base + 3) * 4] = f2tf(v.w);
    }
}

// B perm layout: idx = ((k8*(BN/8) + tn)*32 + lane)*2 + reg
//   lane = (n%8)*4 + (k%4) ; reg = ((k%8)>=4)
template <int BK, int BN>
__device__ __forceinline__ void fill_B(uint32_t* Bs, const float* __restrict__ B,
                                       int k0, int ldb) {
    const int NF4 = BK * BN / 4 / 256;
    int tid = threadIdx.x;
#pragma unroll
    for (int p = 0; p < NF4; p++) {
        int f = tid + p * 256;
        int n4 = f % (BN / 4);
        int k = f / (BN / 4);
        float4 v = *(const float4*)&B[(size_t)(k0 + k) * ldb + n4 * 4];
        int tn = n4 >> 1;
        int k8 = k >> 3;
        int reg = (((k & 7) >= 4) ? 1 : 0);
        int l0 = (n4 & 1) * 16 + (k & 3);   // lane = ((n4&1)*4+q)*4 + (k&3) = l0 + 4q
        uint32_t* dst = Bs + (size_t)((k8 * (BN / 8) + tn) * 32) * 2 + reg;
        dst[(l0 + 0) * 2]  = f2tf(v.x);
        dst[(l0 + 4) * 2]  = f2tf(v.y);
        dst[(l0 + 8) * 2]  = f2tf(v.z);
        dst[(l0 + 12) * 2] = f2tf(v.w);
    }
}

// ---------------- tensor-core GEMM:  C = A[M,K]@B[K,*] (+bias)(lrelu) ----------------
// block tile 256x64 (grid.y = NOUT/64 column split), 8 warps of 64x32
template <int K, bool BIAS, bool LRELU>
__global__ __launch_bounds__(256) void gemm_tc(const float* __restrict__ A,
                                               const float* __restrict__ B,
                                               const float* __restrict__ bias,
                                               float* __restrict__ C, int M,
                                               int ldb, int ldc) {
    const int BM = 256, BK = 32, BN = 64;
    __shared__ __align__(16) uint32_t As[(BK / 8) * (BM / 16) * 32 * 4];
    __shared__ __align__(16) uint32_t Bs[(BK / 8) * (BN / 8) * 32 * 2];
    int tid = threadIdx.x, lane = tid & 31, w = tid >> 5;
    int wm = w >> 1, wn = w & 1;
    int m0 = blockIdx.x * BM;
    int n0 = blockIdx.y * BN;
    const float* Bp = B + n0;

    float4 acc[4][4];
#pragma unroll
    for (int i = 0; i < 4; i++)
#pragma unroll
        for (int j = 0; j < 4; j++) acc[i][j] = make_float4(0.f, 0.f, 0.f, 0.f);

    for (int k0 = 0; k0 < K; k0 += BK) {
        fill_A<BM, BK>(As, A, m0, M, K, k0);
        fill_B<BK, BN>(Bs, Bp, k0, ldb);
        __syncthreads();
#pragma unroll
        for (int k8 = 0; k8 < BK / 8; k8++) {
            uint32_t a[4][4], b[4][2];
#pragma unroll
            for (int i = 0; i < 4; i++)
                *(uint4*)a[i] = *(const uint4*)&As[(size_t)((k8 * (BM / 16) + wm * 4 + i) * 32 + lane) * 4];
#pragma unroll
            for (int j = 0; j < 4; j++)
                *(uint2*)b[j] = *(const uint2*)&Bs[(size_t)((k8 * (BN / 8) + wn * 4 + j) * 32 + lane) * 2];
#pragma unroll
            for (int i = 0; i < 4; i++)
#pragma unroll
                for (int j = 0; j < 4; j++) mma_tf32(acc[i][j], a[i], b[j]);
        }
        __syncthreads();
    }

    int g = lane >> 2, tg = lane & 3;
#pragma unroll
    for (int i = 0; i < 4; i++) {
        int r0 = m0 + wm * 64 + i * 16 + g;
#pragma unroll
        for (int j = 0; j < 4; j++) {
            int c = n0 + wn * 32 + j * 8 + tg * 2;
            float bx = 0.f, by = 0.f;
            if (BIAS) { float2 bb = *(const float2*)&bias[c]; bx = bb.x; by = bb.y; }
            float2 v01 = make_float2(acc[i][j].x + bx, acc[i][j].y + by);
            float2 v23 = make_float2(acc[i][j].z + bx, acc[i][j].w + by);
            if (LRELU) {
                v01.x = lrelu(v01.x); v01.y = lrelu(v01.y);
                v23.x = lrelu(v23.x); v23.y = lrelu(v23.y);
            }
            if (r0 < M)     *(float2*)&C[(size_t)r0 * ldc + c] = v01;
            if (r0 + 8 < M) *(float2*)&C[(size_t)(r0 + 8) * ldc + c] = v23;
        }
    }
}

// ---- dual tensor-core GEMM: out = lrelu(A2@B2 + b2 + lrelu(A1@B1 + b1) + id) ----
// block tile 128x64, 8 warps of 32x32, both GEMMs fused (B* are [K,64])
template <int K>
__global__ __launch_bounds__(256) void dual_gemm_tc(
    const float* __restrict__ A1, const float* __restrict__ B1, const float* __restrict__ b1,
    const float* __restrict__ A2, const float* __restrict__ B2, const float* __restrict__ b2,
    const float* __restrict__ idemb, float* __restrict__ out, int M) {
    const int BM = 128, BK = 16, BN = 64;
    __shared__ __align__(16) uint32_t As1[(BK / 8) * (BM / 16) * 32 * 4];
    __shared__ __align__(16) uint32_t As2[(BK / 8) * (BM / 16) * 32 * 4];
    __shared__ __align__(16) uint32_t Bs1[(BK / 8) * (BN / 8) * 32 * 2];
    __shared__ __align__(16) uint32_t Bs2[(BK / 8) * (BN / 8) * 32 * 2];
    int tid = threadIdx.x, lane = tid & 31, w = tid >> 5;
    int wm = w >> 1, wn = w & 1;
    int m0 = blockIdx.x * BM;

    float4 acc1[2][4], acc2[2][4];
#pragma unroll
    for (int i = 0; i < 2; i++)
#pragma unroll
        for (int j = 0; j < 4; j++) {
            acc1[i][j] = make_float4(0.f, 0.f, 0.f, 0.f);
            acc2[i][j] = make_float4(0.f, 0.f, 0.f, 0.f);
        }

    for (int k0 = 0; k0 < K; k0 += BK) {
        fill_A<BM, BK>(As1, A1, m0, M, K, k0);
        fill_A<BM, BK>(As2, A2, m0, M, K, k0);
        fill_B<BK, BN>(Bs1, B1, k0, BN);
        fill_B<BK, BN>(Bs2, B2, k0, BN);
        __syncthreads();
#pragma unroll
        for (int k8 = 0; k8 < BK / 8; k8++) {
            uint32_t a1[2][4], a2[2][4], bf1[4][2], bf2[4][2];
#pragma unroll
            for (int i = 0; i < 2; i++) {
                int tm = wm * 2 + i;
                *(uint4*)a1[i] = *(const uint4*)&As1[(size_t)((k8 * (BM / 16) + tm) * 32 + lane) * 4];
                *(uint4*)a2[i] = *(const uint4*)&As2[(size_t)((k8 * (BM / 16) + tm) * 32 + lane) * 4];
            }
#pragma unroll
            for (int j = 0; j < 4; j++) {
                int tn = wn * 4 + j;
                *(uint2*)bf1[j] = *(const uint2*)&Bs1[(size_t)((k8 * (BN / 8) + tn) * 32 + lane) * 2];
                *(uint2*)bf2[j] = *(const uint2*)&Bs2[(size_t)((k8 * (BN / 8) + tn) * 32 + lane) * 2];
            }
#pragma unroll
            for (int i = 0; i < 2; i++)
#pragma unroll
                for (int j = 0; j < 4; j++) {
                    mma_tf32(acc1[i][j], a1[i], bf1[j]);
                    mma_tf32(acc2[i][j], a2[i], bf2[j]);
                }
        }
        __syncthreads();
    }

    int g = lane >> 2, tg = lane & 3;
#pragma unroll
    for (int i = 0; i < 2; i++) {
        int r0 = m0 + wm * 32 + i * 16 + g;
#pragma unroll
        for (int j = 0; j < 4; j++) {
            int c = wn * 32 + j * 8 + tg * 2;
            float2 bb1 = *(const float2*)&b1[c];
            float2 bb2 = *(const float2*)&b2[c];
            if (r0 < M) {
                float2 idv = *(const float2*)&idemb[(size_t)r0 * D_X + c];
                float u1 = lrelu(acc1[i][j].x + bb1.x);
                float u2 = lrelu(acc1[i][j].y + bb1.y);
                float o1 = lrelu(acc2[i][j].x + bb2.x + u1 + idv.x);
                float o2 = lrelu(acc2[i][j].y + bb2.y + u2 + idv.y);
                *(float2*)&out[(size_t)r0 * D_X + c] = make_float2(o1, o2);
            }
            if (r0 + 8 < M) {
                float2 idv = *(const float2*)&idemb[(size_t)(r0 + 8) * D_X + c];
                float u1 = lrelu(acc1[i][j].z + bb1.x);
                float u2 = lrelu(acc1[i][j].w + bb1.y);
                float o1 = lrelu(acc2[i][j].z + bb2.x + u1 + idv.x);
                float o2 = lrelu(acc2[i][j].w + bb2.y + u2 + idv.y);
                *(float2*)&out[(size_t)(r0 + 8) * D_X + c] = make_float2(o1, o2);
            }
        }
    }
}

// ---------------- small utility kernels ----------------
__global__ void zero_kernel(float4* __restrict__ p, long n4) {
    long i = (long)blockIdx.x * blockDim.x + threadIdx.x;
    if (i < n4) p[i] = make_float4(0.f, 0.f, 0.f, 0.f);
}

// in: (3, R, C)  ->  out: (3, C, R)
__global__ void transpose_w(const float* __restrict__ in, float* __restrict__ out,
                            int R, int C) {
    int i = blockIdx.x * blockDim.x + threadIdx.x;
    int total = 3 * R * C;
    if (i >= total) return;
    int m = i / (R * C);
    int rem = i - m * R * C;
    int r = rem / C;
    int c = rem - r * C;
    out[m * R * C + c * R + r] = in[i];
}

__global__ void words_scatter(const int* __restrict__ words,
                              const float* __restrict__ word_emb,
                              float* __restrict__ sums, float* __restrict__ cnt, int W) {
    int gw = (int)(((long)blockIdx.x * blockDim.x + threadIdx.x) >> 5);
    int lane = threadIdx.x & 31;
    if (gw >= W) return;
    int item = words[gw];
    int word = words[W + gw];
    float4 v = ((const float4*)(word_emb + (size_t)word * D_LAT))[lane];
    red_add4(sums + (size_t)item * D_LAT + lane * 4, v);
    if (lane == 0) atomicAdd(cnt + item, 1.0f);
}

__global__ void tfeat_div(float* __restrict__ t, const float* __restrict__ cnt) {
    int i = blockIdx.x * blockDim.x + threadIdx.x;
    if (i >= I_NODES * D_LAT) return;
    float c = fmaxf(cnt[i >> 7], 1.0f);
    t[i] = t[i] / c;
}

__global__ void normalize_x(const float* __restrict__ pref_m, float* __restrict__ x) {
    int row = (int)(((long)blockIdx.x * blockDim.x + threadIdx.x) >> 5);
    int lane = threadIdx.x & 31;
    if (row >= N_NODES) return;
    const float* src = (row < U_NODES) ? (pref_m + (size_t)row * D_LAT)
                                       : (x + (size_t)row * D_LAT);
    float4 v = ((const float4*)src)[lane];
    float ss = v.x * v.x + v.y * v.y + v.z * v.z + v.w * v.w;
    ss = warp_sum(ss);
    float s = 1.0f / fmaxf(sqrtf(ss), 1e-12f);
    v.x *= s; v.y *= s; v.z *= s; v.w *= s;
    ((float4*)(x + (size_t)row * D_LAT))[lane] = v;
}

__global__ void scatter_edges128(const int* __restrict__ ei, const float* __restrict__ x,
                                 float* __restrict__ agg, int E) {
    int e = (int)(((long)blockIdx.x * blockDim.x + threadIdx.x) >> 5);
    int lane = threadIdx.x & 31;
    if (e >= E) return;
    int s = ei[e];
    int d = ei[E + e];
    float4 v = ((const float4*)(x + (size_t)s * D_LAT))[lane];
    red_add4(agg + (size_t)d * D_LAT + lane * 4, v);
}

__global__ void scatter_edges64(const int* __restrict__ ei, const float* __restrict__ x,
                                float* __restrict__ agg, int E) {
    int e = (int)(((long)blockIdx.x * blockDim.x + threadIdx.x) >> 5);
    int lane = threadIdx.x & 31;
    if (e >= E) return;
    int s = ei[e];
    int d = ei[E + e];
    float2 v = ((const float2*)(x + (size_t)s * D_X))[lane];
    red_add2(agg + (size_t)d * D_X + lane * 2, v);
}

// ---------------- final scoring ----------------
__global__ void final_kernel(const float* __restrict__ rep,
                             const int* __restrict__ users, const int* __restrict__ pos,
                             const int* __restrict__ neg, float* __restrict__ out, int Bn) {
    int gw = (int)(((long)blockIdx.x * blockDim.x + threadIdx.x) >> 5);
    int lane = threadIdx.x & 31;
    if (gw >= Bn) return;
    int u = users[gw], p = pos[gw], n = neg[gw];
    const size_t stride = (size_t)N_NODES * D_X;
    const float* r0 = rep;
    const float* r1 = rep + stride;
    const float* r2 = rep + 2 * stride;

    auto ld = [&](const float* base, int node) {
        return ((const float2*)(base + (size_t)node * D_X))[lane];
    };
    float2 t_u = ld(r2, u), t_p = ld(r2, p), t_n = ld(r2, n);
    float2 a_u = ld(r0, u), b_u = ld(r1, u);
    float2 a_p = ld(r0, p), b_p = ld(r1, p);
    float2 a_n = ld(r0, n), b_n = ld(r1, n);

    const float third = 1.0f / 3.0f;
    float2 pu = make_float2((a_u.x + b_u.x + t_u.x) * third, (a_u.y + b_u.y + t_u.y) * third);
    float2 pp = make_float2((a_p.x + b_p.x + t_p.x) * third, (a_p.y + b_p.y + t_p.y) * third);
    float2 pn = make_float2((a_n.x + b_n.x + t_n.x) * third, (a_n.y + b_n.y + t_n.y) * third);

    float prep  = t_u.x * t_p.x + t_u.y * t_p.y;
    float pren  = t_u.x * t_n.x + t_u.y * t_n.y;
    float postp = pu.x * pp.x + pu.y * pp.y;
    float postn = pu.x * pn.x + pu.y * pn.y;

    prep = warp_sum(prep);
    pren = warp_sum(pren);
    postp = warp_sum(postp);
    postn = warp_sum(postn);

    if (lane == 0) {
        float sp = 1.0f / (1.0f + expf(-prep));
        float sn = 1.0f / (1.0f + expf(-pren));
        out[gw]          = postp * sp;
        out[Bn + gw]     = postn * sn;
        out[2 * Bn + gw] = prep;
        out[3 * Bn + gw] = pren;
    }
}

// ---------------- host orchestration ----------------
static inline int nblk(long n, int t) { return (int)((n + t - 1) / t); }

extern "C" void kernel_launch(void* const* d_in, const int* in_sizes, int n_in,
                              void* d_out, int out_size) {
    const float* v_feat   = (const float*)d_in[0];
    const float* a_feat   = (const float*)d_in[1];
    const float* word_emb = (const float*)d_in[2];
    const float* id_emb   = (const float*)d_in[3];
    const float* pref     = (const float*)d_in[4];
    const float* mlp_w    = (const float*)d_in[5];
    const float* mlp_b    = (const float*)d_in[6];
    const float* conv1_w  = (const float*)d_in[7];
    const float* lin1_w   = (const float*)d_in[8];
    const float* lin1_b   = (const float*)d_in[9];
    const float* g1_w     = (const float*)d_in[10];
    const float* g1_b     = (const float*)d_in[11];
    const float* conv2_w  = (const float*)d_in[12];
    const float* lin2_w   = (const float*)d_in[13];
    const float* lin2_b   = (const float*)d_in[14];
    const float* g2_w     = (const float*)d_in[15];
    const float* g2_b     = (const float*)d_in[16];
    const int*   edges    = (const int*)d_in[17];
    const int*   words    = (const int*)d_in[18];
    const int*   users    = (const int*)d_in[19];
    const int*   posn     = (const int*)d_in[20];
    const int*   negn     = (const int*)d_in[21];

    const int E  = in_sizes[17] / 2;
    const int W  = in_sizes[18] / 2;
    const int Bn = in_sizes[19];

    float* sc = nullptr;
    cudaGetSymbolAddress((void**)&sc, g_scratch);

    float* tfeat = sc + OFF_TFEAT;
    float* cnt   = sc + OFF_CNT;
    float* x     = sc + OFF_X;
    float* agg   = sc + OFF_AGG;
    float* h     = sc + OFF_H;
    float* x64   = sc + OFF_X64;
    float* h64   = sc + OFF_H64;
    float* rep   = sc + OFF_REP;

    // ---- weight transposes (tiny) ----
    transpose_w<<<nblk(3L * 128 * 128, 256), 256>>>(mlp_w,  sc + OFF_MLPT, 128, 128);
    transpose_w<<<nblk(3L * 64 * 128, 256), 256>>>(lin1_w, sc + OFF_LIN1T, 64, 128);
    transpose_w<<<nblk(3L * 64 * 128, 256), 256>>>(g1_w,   sc + OFF_G1T,   64, 128);
    transpose_w<<<nblk(3L * 64 * 64, 256), 256>>>(lin2_w, sc + OFF_LIN2T, 64, 64);
    transpose_w<<<nblk(3L * 64 * 64, 256), 256>>>(g2_w,   sc + OFF_G2T,   64, 64);

    // ---- t_feat = scatter_mean(word_emb[word_ids], item_ids) ----
    zero_kernel<<<nblk((long)SZ_TFEAT / 4, 256), 256>>>((float4*)tfeat, (long)SZ_TFEAT / 4);
    zero_kernel<<<nblk((long)I_NODES / 4, 256), 256>>>((float4*)cnt, (long)I_NODES / 4);
    words_scatter<<<nblk((long)W * 32, 256), 256>>>(words, word_emb, tfeat, cnt, W);
    tfeat_div<<<nblk((long)I_NODES * D_LAT, 256), 256>>>(tfeat, cnt);

    for (int m = 0; m < 3; m++) {
        const float* feat = (m == 0) ? v_feat : (m == 1) ? a_feat : tfeat;

        // tf = feat @ mlp_w.T + mlp_b   -> x rows [U, N)
        {
            dim3 grid(nblk(I_NODES, 256), 2);
            gemm_tc<128, true, false><<<grid, 256>>>(
                feat, sc + OFF_MLPT + (size_t)m * 128 * 128, mlp_b + m * 128,
                x + (size_t)U_NODES * D_LAT, I_NODES, 128, 128);
        }

        // x = normalize(concat(pref, tf))
        normalize_x<<<nblk((long)N_NODES * 32, 256), 256>>>(
            pref + (size_t)m * U_NODES * D_LAT, x);

        // agg = segment_sum(x[src] -> dst)
        zero_kernel<<<nblk((long)SZ_X / 4, 256), 256>>>((float4*)agg, (long)SZ_X / 4);
        scatter_edges128<<<nblk((long)E * 32, 256), 256>>>(edges, x, agg, E);

        // h = lrelu(agg @ conv1_w)
        {
            dim3 grid(nblk(N_NODES, 256), 2);
            gemm_tc<128, false, true><<<grid, 256>>>(
                agg, conv1_w + (size_t)m * 128 * 128, nullptr, h, N_NODES, 128, 128);
        }

        // x64 = lrelu(h@g1.T + g1b + lrelu(x@l1.T + l1b) + id)
        dual_gemm_tc<128><<<nblk(N_NODES, 128), 256>>>(
            x, sc + OFF_LIN1T + (size_t)m * 128 * 64, lin1_b + m * 64,
            h, sc + OFF_G1T + (size_t)m * 128 * 64, g1_b + m * 64,
            id_emb, x64, N_NODES);

        // layer 2
        zero_kernel<<<nblk((long)SZ_X64 / 4, 256), 256>>>((float4*)agg, (long)SZ_X64 / 4);
        scatter_edges64<<<nblk((long)E * 32, 256), 256>>>(edges, x64, agg, E);

        {
            dim3 grid(nblk(N_NODES, 256), 1);
            gemm_tc<64, false, true><<<grid, 256>>>(
                agg, conv2_w + (size_t)m * 64 * 64, nullptr, h64, N_NODES, 64, 64);
        }

        dual_gemm_tc<64><<<nblk(N_NODES, 128), 256>>>(
            x64, sc + OFF_LIN2T + (size_t)m * 64 * 64, lin2_b + m * 64,
            h64, sc + OFF_G2T + (size_t)m * 64 * 64, g2_b + m * 64,
            id_emb, rep + (size_t)m * N_NODES * D_X, N_NODES);
    }

    final_kernel<<<nblk((long)Bn * 32, 256), 256>>>(rep, users, posn, negn,
                                                    (float*)d_out, Bn);
}

// round 5
// speedup vs baseline: 1.3316x; 1.1312x over previous
#include <cuda_runtime.h>
#include <cuda_bf16.h>
#include <math.h>
#include <stdint.h>

// ---------------- problem constants ----------------
#define U_NODES 40000
#define I_NODES 30000
#define N_NODES 70000
#define D_LAT   128
#define D_X     64

// ---------------- scratch layout (floats) ----------------
static const size_t SZ_X     = (size_t)N_NODES * D_LAT;      // 8,960,000
static const size_t SZ_X64   = (size_t)N_NODES * D_X;        // 4,480,000

static const size_t OFF_TFEAT = 0;                     // 3,840,000 (I*128)
static const size_t OFF_CNT   = 3840000;
static const size_t OFF_MLPT  = 3872000;               // 3*16384
static const size_t OFF_LIN1T = OFF_MLPT  + 3 * 128 * 128;
static const size_t OFF_G1T   = OFF_LIN1T + 3 * 128 * 64;
static const size_t OFF_LIN2T = OFF_G1T   + 3 * 128 * 64;
static const size_t OFF_G2T   = OFF_LIN2T + 3 * 64 * 64;
// three big regions, each 3*SZ_X, with lifetime-based reuse:
//  R_X   : x (L1)            -> rep (dual2 out)
//  R_AGG : agg128 (L1)       -> x64 [0..3*SZ_X64) + agg64 [3*SZ_X64..6*SZ_X64)
//  R_H   : h (L1)            -> h64 (L2)
static const size_t R_X   = 4000000;
static const size_t R_AGG = R_X + 3 * SZ_X;            // 30,880,000
static const size_t R_H   = R_AGG + 3 * SZ_X;          // 57,760,000
static const size_t SCRATCH_TOTAL = R_H + 3 * SZ_X;    // 84,640,000 floats (~339 MB)

__device__ float g_scratch[SCRATCH_TOTAL];

// ---------------- helpers ----------------
__device__ __forceinline__ float lrelu(float v) { return v >= 0.0f ? v : 0.01f * v; }

__device__ __forceinline__ void red_add4(float* p, float4 v) {
    asm volatile("red.global.add.v4.f32 [%0], {%1,%2,%3,%4};"
                 :: "l"(p), "f"(v.x), "f"(v.y), "f"(v.z), "f"(v.w) : "memory");
}
__device__ __forceinline__ void red_add2(float* p, float2 v) {
    asm volatile("red.global.add.v2.f32 [%0], {%1,%2};"
                 :: "l"(p), "f"(v.x), "f"(v.y) : "memory");
}

__device__ __forceinline__ float warp_sum(float v) {
#pragma unroll
    for (int o = 16; o > 0; o >>= 1) v += __shfl_xor_sync(0xFFFFFFFFu, v, o);
    return v;
}

__device__ __forceinline__ uint32_t f2tf(float f) {
    uint32_t r;
    asm("cvt.rna.tf32.f32 %0, %1;" : "=r"(r) : "f"(f));
    return r;
}

__device__ __forceinline__ void mma_tf32(float4& d, const uint32_t* a, const uint32_t* b) {
    asm volatile(
        "mma.sync.aligned.m16n8k8.row.col.f32.tf32.tf32.f32 "
        "{%0,%1,%2,%3}, {%4,%5,%6,%7}, {%8,%9}, {%0,%1,%2,%3};"
        : "+f"(d.x), "+f"(d.y), "+f"(d.z), "+f"(d.w)
        : "r"(a[0]), "r"(a[1]), "r"(a[2]), "r"(a[3]), "r"(b[0]), "r"(b[1]));
}

// ---- smem tile fills (fragment-order layout) ----
template <int BM, int BK>
__device__ __forceinline__ void fill_A(uint32_t* As, const float* __restrict__ A,
                                       int m0, int M, int lda, int k0) {
    const int NF4 = BM * BK / 4 / 256;
    int tid = threadIdx.x;
#pragma unroll
    for (int p = 0; p < NF4; p++) {
        int f = tid + p * 256;
        int m = f / (BK / 4);
        int k4 = f % (BK / 4);
        int gm = m0 + m;
        float4 v = make_float4(0.f, 0.f, 0.f, 0.f);
        if (gm < M) v = *(const float4*)&A[(size_t)gm * lda + k0 + k4 * 4];
        int k8 = k4 >> 1;
        int tm = m >> 4;
        int lane_base = (m & 7) * 4;
        int reg = (((m & 15) >= 8) ? 1 : 0) + ((k4 & 1) ? 2 : 0);
        uint32_t* dst = As + (size_t)((k8 * (BM / 16) + tm) * 32) * 4 + reg;
        dst[(lane_base + 0) * 4] = f2tf(v.x);
        dst[(lane_base + 1) * 4] = f2tf(v.y);
        dst[(lane_base + 2) * 4] = f2tf(v.z);
        dst[(lane_base + 3) * 4] = f2tf(v.w);
    }
}

template <int BK, int BN>
__device__ __forceinline__ void fill_B(uint32_t* Bs, const float* __restrict__ B,
                                       int k0, int ldb) {
    const int NF4 = BK * BN / 4 / 256;
    int tid = threadIdx.x;
#pragma unroll
    for (int p = 0; p < NF4; p++) {
        int f = tid + p * 256;
        int n4 = f % (BN / 4);
        int k = f / (BN / 4);
        float4 v = *(const float4*)&B[(size_t)(k0 + k) * ldb + n4 * 4];
        int tn = n4 >> 1;
        int k8 = k >> 3;
        int reg = (((k & 7) >= 4) ? 1 : 0);
        int l0 = (n4 & 1) * 16 + (k & 3);
        uint32_t* dst = Bs + (size_t)((k8 * (BN / 8) + tn) * 32) * 2 + reg;
        dst[(l0 + 0) * 2]  = f2tf(v.x);
        dst[(l0 + 4) * 2]  = f2tf(v.y);
        dst[(l0 + 8) * 2]  = f2tf(v.z);
        dst[(l0 + 12) * 2] = f2tf(v.w);
    }
}

// ---------- batched TC GEMM: per z: C_z = A_z[M,K] @ B_z[K,*] (+bias)(lrelu) ----------
template <int K, bool BIAS, bool LRELU>
__global__ __launch_bounds__(256) void gemm_tc_b(
    const float* __restrict__ Aa, const float* __restrict__ Ab, const float* __restrict__ Ac,
    const float* __restrict__ B, size_t sB,
    const float* __restrict__ bias, size_t sbias,
    float* __restrict__ C, size_t sC, int M, int ldb, int ldc) {
    const int BM = 256, BK = 32, BN = 64;
    __shared__ __align__(16) uint32_t As[(BK / 8) * (BM / 16) * 32 * 4];
    __shared__ __align__(16) uint32_t Bs[(BK / 8) * (BN / 8) * 32 * 2];
    int z = blockIdx.z;
    const float* A = (z == 0) ? Aa : (z == 1) ? Ab : Ac;
    const float* Bz = B + (size_t)z * sB;
    const float* biasz = BIAS ? bias + (size_t)z * sbias : nullptr;
    float* Cz = C + (size_t)z * sC;

    int tid = threadIdx.x, lane = tid & 31, w = tid >> 5;
    int wm = w >> 1, wn = w & 1;
    int m0 = blockIdx.x * BM;
    int n0 = blockIdx.y * BN;
    const float* Bp = Bz + n0;

    float4 acc[4][4];
#pragma unroll
    for (int i = 0; i < 4; i++)
#pragma unroll
        for (int j = 0; j < 4; j++) acc[i][j] = make_float4(0.f, 0.f, 0.f, 0.f);

    for (int k0 = 0; k0 < K; k0 += BK) {
        fill_A<BM, BK>(As, A, m0, M, K, k0);
        fill_B<BK, BN>(Bs, Bp, k0, ldb);
        __syncthreads();
#pragma unroll
        for (int k8 = 0; k8 < BK / 8; k8++) {
            uint32_t a[4][4], b[4][2];
#pragma unroll
            for (int i = 0; i < 4; i++)
                *(uint4*)a[i] = *(const uint4*)&As[(size_t)((k8 * (BM / 16) + wm * 4 + i) * 32 + lane) * 4];
#pragma unroll
            for (int j = 0; j < 4; j++)
                *(uint2*)b[j] = *(const uint2*)&Bs[(size_t)((k8 * (BN / 8) + wn * 4 + j) * 32 + lane) * 2];
#pragma unroll
            for (int i = 0; i < 4; i++)
#pragma unroll
                for (int j = 0; j < 4; j++) mma_tf32(acc[i][j], a[i], b[j]);
        }
        __syncthreads();
    }

    int g = lane >> 2, tg = lane & 3;
#pragma unroll
    for (int i = 0; i < 4; i++) {
        int r0 = m0 + wm * 64 + i * 16 + g;
#pragma unroll
        for (int j = 0; j < 4; j++) {
            int c = n0 + wn * 32 + j * 8 + tg * 2;
            float bx = 0.f, by = 0.f;
            if (BIAS) { float2 bb = *(const float2*)&biasz[c]; bx = bb.x; by = bb.y; }
            float2 v01 = make_float2(acc[i][j].x + bx, acc[i][j].y + by);
            float2 v23 = make_float2(acc[i][j].z + bx, acc[i][j].w + by);
            if (LRELU) {
                v01.x = lrelu(v01.x); v01.y = lrelu(v01.y);
                v23.x = lrelu(v23.x); v23.y = lrelu(v23.y);
            }
            if (r0 < M)     *(float2*)&Cz[(size_t)r0 * ldc + c] = v01;
            if (r0 + 8 < M) *(float2*)&Cz[(size_t)(r0 + 8) * ldc + c] = v23;
        }
    }
}

// ---- batched dual GEMM: out_z = lrelu(A2_z@B2_z + b2 + lrelu(A1_z@B1_z + b1) + id) ----
template <int K>
__global__ __launch_bounds__(256) void dual_gemm_tc_b(
    const float* __restrict__ A1, size_t sA1,
    const float* __restrict__ B1, size_t sB1, const float* __restrict__ b1, size_t sb1,
    const float* __restrict__ A2, size_t sA2,
    const float* __restrict__ B2, size_t sB2, const float* __restrict__ b2, size_t sb2,
    const float* __restrict__ idemb, float* __restrict__ out, size_t sOut, int M) {
    const int BM = 128, BK = 16, BN = 64;
    __shared__ __align__(16) uint32_t As1[(BK / 8) * (BM / 16) * 32 * 4];
    __shared__ __align__(16) uint32_t As2[(BK / 8) * (BM / 16) * 32 * 4];
    __shared__ __align__(16) uint32_t Bs1[(BK / 8) * (BN / 8) * 32 * 2];
    __shared__ __align__(16) uint32_t Bs2[(BK / 8) * (BN / 8) * 32 * 2];
    int z = blockIdx.z;
    const float* A1z = A1 + (size_t)z * sA1;
    const float* A2z = A2 + (size_t)z * sA2;
    const float* B1z = B1 + (size_t)z * sB1;
    const float* B2z = B2 + (size_t)z * sB2;
    const float* b1z = b1 + (size_t)z * sb1;
    const float* b2z = b2 + (size_t)z * sb2;
    float* outz = out + (size_t)z * sOut;

    int tid = threadIdx.x, lane = tid & 31, w = tid >> 5;
    int wm = w >> 1, wn = w & 1;
    int m0 = blockIdx.x * BM;

    float4 acc1[2][4], acc2[2][4];
#pragma unroll
    for (int i = 0; i < 2; i++)
#pragma unroll
        for (int j = 0; j < 4; j++) {
            acc1[i][j] = make_float4(0.f, 0.f, 0.f, 0.f);
            acc2[i][j] = make_float4(0.f, 0.f, 0.f, 0.f);
        }

    for (int k0 = 0; k0 < K; k0 += BK) {
        fill_A<BM, BK>(As1, A1z, m0, M, K, k0);
        fill_A<BM, BK>(As2, A2z, m0, M, K, k0);
        fill_B<BK, BN>(Bs1, B1z, k0, BN);
        fill_B<BK, BN>(Bs2, B2z, k0, BN);
        __syncthreads();
#pragma unroll
        for (int k8 = 0; k8 < BK / 8; k8++) {
            uint32_t a1[2][4], a2[2][4], bf1[4][2], bf2[4][2];
#pragma unroll
            for (int i = 0; i < 2; i++) {
                int tm = wm * 2 + i;
                *(uint4*)a1[i] = *(const uint4*)&As1[(size_t)((k8 * (BM / 16) + tm) * 32 + lane) * 4];
                *(uint4*)a2[i] = *(const uint4*)&As2[(size_t)((k8 * (BM / 16) + tm) * 32 + lane) * 4];
            }
#pragma unroll
            for (int j = 0; j < 4; j++) {
                int tn = wn * 4 + j;
                *(uint2*)bf1[j] = *(const uint2*)&Bs1[(size_t)((k8 * (BN / 8) + tn) * 32 + lane) * 2];
                *(uint2*)bf2[j] = *(const uint2*)&Bs2[(size_t)((k8 * (BN / 8) + tn) * 32 + lane) * 2];
            }
#pragma unroll
            for (int i = 0; i < 2; i++)
#pragma unroll
                for (int j = 0; j < 4; j++) {
                    mma_tf32(acc1[i][j], a1[i], bf1[j]);
                    mma_tf32(acc2[i][j], a2[i], bf2[j]);
                }
        }
        __syncthreads();
    }

    int g = lane >> 2, tg = lane & 3;
#pragma unroll
    for (int i = 0; i < 2; i++) {
        int r0 = m0 + wm * 32 + i * 16 + g;
#pragma unroll
        for (int j = 0; j < 4; j++) {
            int c = wn * 32 + j * 8 + tg * 2;
            float2 bb1 = *(const float2*)&b1z[c];
            float2 bb2 = *(const float2*)&b2z[c];
            if (r0 < M) {
                float2 idv = *(const float2*)&idemb[(size_t)r0 * D_X + c];
                float u1 = lrelu(acc1[i][j].x + bb1.x);
                float u2 = lrelu(acc1[i][j].y + bb1.y);
                float o1 = lrelu(acc2[i][j].x + bb2.x + u1 + idv.x);
                float o2 = lrelu(acc2[i][j].y + bb2.y + u2 + idv.y);
                *(float2*)&outz[(size_t)r0 * D_X + c] = make_float2(o1, o2);
            }
            if (r0 + 8 < M) {
                float2 idv = *(const float2*)&idemb[(size_t)(r0 + 8) * D_X + c];
                float u1 = lrelu(acc1[i][j].z + bb1.x);
                float u2 = lrelu(acc1[i][j].w + bb1.y);
                float o1 = lrelu(acc2[i][j].z + bb2.x + u1 + idv.x);
                float o2 = lrelu(acc2[i][j].w + bb2.y + u2 + idv.y);
                *(float2*)&outz[(size_t)(r0 + 8) * D_X + c] = make_float2(o1, o2);
            }
        }
    }
}

// ---------------- small utility kernels ----------------
__global__ void zero_kernel(float4* __restrict__ p, long n4) {
    long i = (long)blockIdx.x * blockDim.x + threadIdx.x;
    if (i < n4) p[i] = make_float4(0.f, 0.f, 0.f, 0.f);
}

// all five weight transposes in one launch
__global__ void transpose_all(const float* __restrict__ w0, const float* __restrict__ w1,
                              const float* __restrict__ w2, const float* __restrict__ w3,
                              const float* __restrict__ w4,
                              float* __restrict__ o0, float* __restrict__ o1,
                              float* __restrict__ o2, float* __restrict__ o3,
                              float* __restrict__ o4) {
    int i = blockIdx.x * blockDim.x + threadIdx.x;
    const float* in; float* out; int R, C;
    if (i < 49152)       { in = w0; out = o0; R = 128; C = 128; }
    else if (i < 73728)  { i -= 49152;  in = w1; out = o1; R = 64; C = 128; }
    else if (i < 98304)  { i -= 73728;  in = w2; out = o2; R = 64; C = 128; }
    else if (i < 110592) { i -= 98304;  in = w3; out = o3; R = 64; C = 64; }
    else if (i < 122880) { i -= 110592; in = w4; out = o4; R = 64; C = 64; }
    else return;
    int m = i / (R * C);
    int rem = i - m * R * C;
    int r = rem / C;
    int c = rem - r * C;
    out[m * R * C + c * R + r] = in[i];
}

__global__ void words_scatter(const int* __restrict__ words,
                              const float* __restrict__ word_emb,
                              float* __restrict__ sums, float* __restrict__ cnt, int W) {
    int gw = (int)(((long)blockIdx.x * blockDim.x + threadIdx.x) >> 5);
    int lane = threadIdx.x & 31;
    if (gw >= W) return;
    int item = words[gw];
    int word = words[W + gw];
    float4 v = ((const float4*)(word_emb + (size_t)word * D_LAT))[lane];
    red_add4(sums + (size_t)item * D_LAT + lane * 4, v);
    if (lane == 0) atomicAdd(cnt + item, 1.0f);
}

__global__ void tfeat_div(float* __restrict__ t, const float* __restrict__ cnt) {
    int i = blockIdx.x * blockDim.x + threadIdx.x;
    if (i >= I_NODES * D_LAT) return;
    float c = fmaxf(cnt[i >> 7], 1.0f);
    t[i] = t[i] / c;
}

// batched over modalities via blockIdx.y
__global__ void normalize_x_b(const float* __restrict__ pref, float* __restrict__ xbase) {
    int row = (int)(((long)blockIdx.x * blockDim.x + threadIdx.x) >> 5);
    int lane = threadIdx.x & 31;
    if (row >= N_NODES) return;
    int z = blockIdx.y;
    float* x = xbase + (size_t)z * SZ_X;
    const float* pref_m = pref + (size_t)z * U_NODES * D_LAT;
    const float* src = (row < U_NODES) ? (pref_m + (size_t)row * D_LAT)
                                       : (x + (size_t)row * D_LAT);
    float4 v = ((const float4*)src)[lane];
    float ss = v.x * v.x + v.y * v.y + v.z * v.z + v.w * v.w;
    ss = warp_sum(ss);
    float s = 1.0f / fmaxf(sqrtf(ss), 1e-12f);
    v.x *= s; v.y *= s; v.z *= s; v.w *= s;
    ((float4*)(x + (size_t)row * D_LAT))[lane] = v;
}

// one warp per UNIQUE edge pair: does both directions
__global__ void scatter_pairs128(const int* __restrict__ ei, int E,
                                 const float* __restrict__ x, float* __restrict__ agg,
                                 int Eh) {
    int e = (int)(((long)blockIdx.x * blockDim.x + threadIdx.x) >> 5);
    int lane = threadIdx.x & 31;
    if (e >= Eh) return;
    int u = ei[e];
    int it = ei[E + e];
    float4 xu = ((const float4*)(x + (size_t)u * D_LAT))[lane];
    float4 xi = ((const float4*)(x + (size_t)it * D_LAT))[lane];
    red_add4(agg + (size_t)it * D_LAT + lane * 4, xu);
    red_add4(agg + (size_t)u * D_LAT + lane * 4, xi);
}

__global__ void scatter_pairs64(const int* __restrict__ ei, int E,
                                const float* __restrict__ x, float* __restrict__ agg,
                                int Eh) {
    int e = (int)(((long)blockIdx.x * blockDim.x + threadIdx.x) >> 5);
    int lane = threadIdx.x & 31;
    if (e >= Eh) return;
    int u = ei[e];
    int it = ei[E + e];
    float2 xu = ((const float2*)(x + (size_t)u * D_X))[lane];
    float2 xi = ((const float2*)(x + (size_t)it * D_X))[lane];
    red_add2(agg + (size_t)it * D_X + lane * 2, xu);
    red_add2(agg + (size_t)u * D_X + lane * 2, xi);
}

// ---------------- final scoring ----------------
__global__ void final_kernel(const float* __restrict__ rep,
                             const int* __restrict__ users, const int* __restrict__ pos,
                             const int* __restrict__ neg, float* __restrict__ out, int Bn) {
    int gw = (int)(((long)blockIdx.x * blockDim.x + threadIdx.x) >> 5);
    int lane = threadIdx.x & 31;
    if (gw >= Bn) return;
    int u = users[gw], p = pos[gw], n = neg[gw];
    const size_t stride = (size_t)N_NODES * D_X;
    const float* r0 = rep;
    const float* r1 = rep + stride;
    const float* r2 = rep + 2 * stride;

    auto ld = [&](const float* base, int node) {
        return ((const float2*)(base + (size_t)node * D_X))[lane];
    };
    float2 t_u = ld(r2, u), t_p = ld(r2, p), t_n = ld(r2, n);
    float2 a_u = ld(r0, u), b_u = ld(r1, u);
    float2 a_p = ld(r0, p), b_p = ld(r1, p);
    float2 a_n = ld(r0, n), b_n = ld(r1, n);

    const float third = 1.0f / 3.0f;
    float2 pu = make_float2((a_u.x + b_u.x + t_u.x) * third, (a_u.y + b_u.y + t_u.y) * third);
    float2 pp = make_float2((a_p.x + b_p.x + t_p.x) * third, (a_p.y + b_p.y + t_p.y) * third);
    float2 pn = make_float2((a_n.x + b_n.x + t_n.x) * third, (a_n.y + b_n.y + t_n.y) * third);

    float prep  = t_u.x * t_p.x + t_u.y * t_p.y;
    float pren  = t_u.x * t_n.x + t_u.y * t_n.y;
    float postp = pu.x * pp.x + pu.y * pp.y;
    float postn = pu.x * pn.x + pu.y * pn.y;

    prep = warp_sum(prep);
    pren = warp_sum(pren);
    postp = warp_sum(postp);
    postn = warp_sum(postn);

    if (lane == 0) {
        float sp = 1.0f / (1.0f + expf(-prep));
        float sn = 1.0f / (1.0f + expf(-pren));
        out[gw]          = postp * sp;
        out[Bn + gw]     = postn * sn;
        out[2 * Bn + gw] = prep;
        out[3 * Bn + gw] = pren;
    }
}

// ---------------- host orchestration ----------------
static inline int nblk(long n, int t) { return (int)((n + t - 1) / t); }

extern "C" void kernel_launch(void* const* d_in, const int* in_sizes, int n_in,
                              void* d_out, int out_size) {
    const float* v_feat   = (const float*)d_in[0];
    const float* a_feat   = (const float*)d_in[1];
    const float* word_emb = (const float*)d_in[2];
    const float* id_emb   = (const float*)d_in[3];
    const float* pref     = (const float*)d_in[4];
    const float* mlp_w    = (const float*)d_in[5];
    const float* mlp_b    = (const float*)d_in[6];
    const float* conv1_w  = (const float*)d_in[7];
    const float* lin1_w   = (const float*)d_in[8];
    const float* lin1_b   = (const float*)d_in[9];
    const float* g1_w     = (const float*)d_in[10];
    const float* g1_b     = (const float*)d_in[11];
    const float* conv2_w  = (const float*)d_in[12];
    const float* lin2_w   = (const float*)d_in[13];
    const float* lin2_b   = (const float*)d_in[14];
    const float* g2_w     = (const float*)d_in[15];
    const float* g2_b     = (const float*)d_in[16];
    const int*   edges    = (const int*)d_in[17];
    const int*   words    = (const int*)d_in[18];
    const int*   users    = (const int*)d_in[19];
    const int*   posn     = (const int*)d_in[20];
    const int*   negn     = (const int*)d_in[21];

    const int E  = in_sizes[17] / 2;   // 500000
    const int Eh = E / 2;              // 250000 unique pairs (edge list is doubled)
    const int W  = in_sizes[18] / 2;   // 600000
    const int Bn = in_sizes[19];       // 2048

    float* sc = nullptr;
    cudaGetSymbolAddress((void**)&sc, g_scratch);

    float* tfeat = sc + OFF_TFEAT;
    float* cnt   = sc + OFF_CNT;
    float* x     = sc + R_X;                       // stride SZ_X   (layer 1)
    float* rep   = sc + R_X;                       // stride SZ_X64 (dual2 out; x dead)
    float* agg   = sc + R_AGG;                     // stride SZ_X   (layer 1)
    float* x64   = sc + R_AGG;                     // stride SZ_X64 (agg128 dead)
    float* agg64 = sc + R_AGG + 3 * SZ_X64;        // stride SZ_X64
    float* h     = sc + R_H;                       // stride SZ_X   (layer 1)
    float* h64   = sc + R_H;                       // stride SZ_X64 (layer 2)

    // 1: all weight transposes
    transpose_all<<<nblk(122880, 256), 256>>>(mlp_w, lin1_w, g1_w, lin2_w, g2_w,
                                              sc + OFF_MLPT, sc + OFF_LIN1T, sc + OFF_G1T,
                                              sc + OFF_LIN2T, sc + OFF_G2T);
    // 2: zero tfeat + cnt (contiguous range)
    zero_kernel<<<nblk((long)OFF_MLPT / 4, 256), 256>>>((float4*)tfeat, (long)OFF_MLPT / 4);
    // 3-4: t_feat scatter-mean
    words_scatter<<<nblk((long)W * 32, 256), 256>>>(words, word_emb, tfeat, cnt, W);
    tfeat_div<<<nblk((long)I_NODES * D_LAT, 256), 256>>>(tfeat, cnt);
    // 5: zero all three agg (128-dim) buffers
    zero_kernel<<<nblk((long)(3 * SZ_X) / 4, 256), 256>>>((float4*)agg, (long)(3 * SZ_X) / 4);

    // 6: batched mlp GEMM -> x_z rows [U, N)
    {
        dim3 grid(nblk(I_NODES, 256), 2, 3);
        gemm_tc_b<128, true, false><<<grid, 256>>>(
            v_feat, a_feat, tfeat,
            sc + OFF_MLPT, 128 * 128, mlp_b, 128,
            x + (size_t)U_NODES * D_LAT, SZ_X, I_NODES, 128, 128);
    }
    // 7: batched normalize
    {
        dim3 grid(nblk((long)N_NODES * 32, 256), 3);
        normalize_x_b<<<grid, 256>>>(pref, x);
    }
    // 8-10: per-modality edge scatter (kept sequential for L2 residency)
    for (int m = 0; m < 3; m++)
        scatter_pairs128<<<nblk((long)Eh * 32, 256), 256>>>(
            edges, E, x + (size_t)m * SZ_X, agg + (size_t)m * SZ_X, Eh);

    // 11: batched conv1  h_z = lrelu(agg_z @ conv1_w_z)
    {
        dim3 grid(nblk(N_NODES, 256), 2, 3);
        gemm_tc_b<128, false, true><<<grid, 256>>>(
            agg, agg + SZ_X, agg + 2 * SZ_X,
            conv1_w, 128 * 128, nullptr, 0,
            h, SZ_X, N_NODES, 128, 128);
    }
    // 12: batched dual1  x64_z = lrelu(h@g1.T + g1b + lrelu(x@l1.T + l1b) + id)
    //     writes x64 into R_AGG (agg128 dead after conv1)
    {
        dim3 grid(nblk(N_NODES, 128), 1, 3);
        dual_gemm_tc_b<128><<<grid, 256>>>(
            x, SZ_X, sc + OFF_LIN1T, 128 * 64, lin1_b, 64,
            h, SZ_X, sc + OFF_G1T, 128 * 64, g1_b, 64,
            id_emb, x64, SZ_X64, N_NODES);
    }
    // 13: zero agg64 (second half of R_AGG)
    zero_kernel<<<nblk((long)(3 * SZ_X64) / 4, 256), 256>>>((float4*)agg64, (long)(3 * SZ_X64) / 4);
    // 14-16: per-modality 64-dim scatter
    for (int m = 0; m < 3; m++)
        scatter_pairs64<<<nblk((long)Eh * 32, 256), 256>>>(
            edges, E, x64 + (size_t)m * SZ_X64, agg64 + (size_t)m * SZ_X64, Eh);

    // 17: batched conv2
    {
        dim3 grid(nblk(N_NODES, 256), 1, 3);
        gemm_tc_b<64, false, true><<<grid, 256>>>(
            agg64, agg64 + SZ_X64, agg64 + 2 * SZ_X64,
            conv2_w, 64 * 64, nullptr, 0,
            h64, SZ_X64, N_NODES, 64, 64);
    }
    // 18: batched dual2 -> rep (into R_X; x dead)
    {
        dim3 grid(nblk(N_NODES, 128), 1, 3);
        dual_gemm_tc_b<64><<<grid, 256>>>(
            x64, SZ_X64, sc + OFF_LIN2T, 64 * 64, lin2_b, 64,
            h64, SZ_X64, sc + OFF_G2T, 64 * 64, g2_b, 64,
            id_emb, rep, SZ_X64, N_NODES);
    }
    // 19: final scoring
    final_kernel<<<nblk((long)Bn * 32, 256), 256>>>(rep, users, posn, negn,
                                                    (float*)d_out, Bn);
}

// round 6
// speedup vs baseline: 1.4899x; 1.1189x over previous
#include <cuda_runtime.h>
#include <cuda_bf16.h>
#include <math.h>
#include <stdint.h>

// ---------------- problem constants ----------------
#define U_NODES 40000
#define I_NODES 30000
#define N_NODES 70000
#define D_LAT   128
#define D_X     64

// ---------------- scratch layout (floats) ----------------
static const size_t SZ_X     = (size_t)N_NODES * D_LAT;      // 8,960,000
static const size_t SZ_X64   = (size_t)N_NODES * D_X;        // 4,480,000

static const size_t OFF_TFEAT = 0;                     // I*128
static const size_t OFF_MLPT  = 3872000;
static const size_t OFF_LIN1T = OFF_MLPT  + 3 * 128 * 128;
static const size_t OFF_G1T   = OFF_LIN1T + 3 * 128 * 64;
static const size_t OFF_LIN2T = OFF_G1T   + 3 * 128 * 64;
static const size_t OFF_G2T   = OFF_LIN2T + 3 * 64 * 64;
// big regions with lifetime reuse (as in R4):
static const size_t R_X   = 4000000;                   // x (L1) -> rep (dual2 out)
static const size_t R_AGG = R_X + 3 * SZ_X;            // agg128 -> x64 + agg64
static const size_t R_H   = R_AGG + 3 * SZ_X;          // h -> h64
static const size_t OFF_CSR = R_H + 3 * SZ_X;          // int scratch (~0.7M ints)
static const size_t SCRATCH_TOTAL = OFF_CSR + 700000;  // ~341 MB

__device__ float g_scratch[SCRATCH_TOTAL];

// int-scratch offsets (in ints, within OFF_CSR region)
#define ICUR  0        // cursor / deg (70001)
#define IRP   70016    // row_ptr (70001)
#define IBSUM 140032   // block sums (280)
#define ICOL  140320   // col indices (500000)
#define IWRP  640320   // words row_ptr (30001)

// ---------------- helpers ----------------
__device__ __forceinline__ float lrelu(float v) { return v >= 0.0f ? v : 0.01f * v; }

__device__ __forceinline__ float warp_sum(float v) {
#pragma unroll
    for (int o = 16; o > 0; o >>= 1) v += __shfl_xor_sync(0xFFFFFFFFu, v, o);
    return v;
}

__device__ __forceinline__ uint32_t f2tf(float f) {
    uint32_t r;
    asm("cvt.rna.tf32.f32 %0, %1;" : "=r"(r) : "f"(f));
    return r;
}

__device__ __forceinline__ void mma_tf32(float4& d, const uint32_t* a, const uint32_t* b) {
    asm volatile(
        "mma.sync.aligned.m16n8k8.row.col.f32.tf32.tf32.f32 "
        "{%0,%1,%2,%3}, {%4,%5,%6,%7}, {%8,%9}, {%0,%1,%2,%3};"
        : "+f"(d.x), "+f"(d.y), "+f"(d.z), "+f"(d.w)
        : "r"(a[0]), "r"(a[1]), "r"(a[2]), "r"(a[3]), "r"(b[0]), "r"(b[1]));
}

__device__ __forceinline__ void acc4(float4& a, float4 v) {
    a.x += v.x; a.y += v.y; a.z += v.z; a.w += v.w;
}
__device__ __forceinline__ void acc2(float2& a, float2 v) { a.x += v.x; a.y += v.y; }

// ---- smem tile fills (fragment-order layout, validated in R2) ----
template <int BM, int BK>
__device__ __forceinline__ void fill_A(uint32_t* As, const float* __restrict__ A,
                                       int m0, int M, int lda, int k0) {
    const int NF4 = BM * BK / 4 / 256;
    int tid = threadIdx.x;
#pragma unroll
    for (int p = 0; p < NF4; p++) {
        int f = tid + p * 256;
        int m = f / (BK / 4);
        int k4 = f % (BK / 4);
        int gm = m0 + m;
        float4 v = make_float4(0.f, 0.f, 0.f, 0.f);
        if (gm < M) v = *(const float4*)&A[(size_t)gm * lda + k0 + k4 * 4];
        int k8 = k4 >> 1;
        int tm = m >> 4;
        int lane_base = (m & 7) * 4;
        int reg = (((m & 15) >= 8) ? 1 : 0) + ((k4 & 1) ? 2 : 0);
        uint32_t* dst = As + (size_t)((k8 * (BM / 16) + tm) * 32) * 4 + reg;
        dst[(lane_base + 0) * 4] = f2tf(v.x);
        dst[(lane_base + 1) * 4] = f2tf(v.y);
        dst[(lane_base + 2) * 4] = f2tf(v.z);
        dst[(lane_base + 3) * 4] = f2tf(v.w);
    }
}

template <int BK, int BN>
__device__ __forceinline__ void fill_B(uint32_t* Bs, const float* __restrict__ B,
                                       int k0, int ldb) {
    const int NF4 = BK * BN / 4 / 256;
    int tid = threadIdx.x;
#pragma unroll
    for (int p = 0; p < NF4; p++) {
        int f = tid + p * 256;
        int n4 = f % (BN / 4);
        int k = f / (BN / 4);
        float4 v = *(const float4*)&B[(size_t)(k0 + k) * ldb + n4 * 4];
        int tn = n4 >> 1;
        int k8 = k >> 3;
        int reg = (((k & 7) >= 4) ? 1 : 0);
        int l0 = (n4 & 1) * 16 + (k & 3);
        uint32_t* dst = Bs + (size_t)((k8 * (BN / 8) + tn) * 32) * 2 + reg;
        dst[(l0 + 0) * 2]  = f2tf(v.x);
        dst[(l0 + 4) * 2]  = f2tf(v.y);
        dst[(l0 + 8) * 2]  = f2tf(v.z);
        dst[(l0 + 12) * 2] = f2tf(v.w);
    }
}

// ---------- batched TC GEMM: BM=128, full-N tile (A read once) ----------
template <int K, int BN, bool BIAS, bool LRELU>
__global__ __launch_bounds__(256) void gemm_tc_b(
    const float* __restrict__ Aa, const float* __restrict__ Ab, const float* __restrict__ Ac,
    const float* __restrict__ B, size_t sB,
    const float* __restrict__ bias, size_t sbias,
    float* __restrict__ C, size_t sC, int M, int ldb, int ldc) {
    const int BM = 128, BK = 32;
    const int NJ = BN / 16;   // frags per warp in N (8 for BN=128, 4 for BN=64)
    __shared__ __align__(16) uint32_t As[(BK / 8) * (BM / 16) * 32 * 4];
    __shared__ __align__(16) uint32_t Bs[(BK / 8) * (BN / 8) * 32 * 2];
    int z = blockIdx.z;
    const float* A = (z == 0) ? Aa : (z == 1) ? Ab : Ac;
    const float* Bz = B + (size_t)z * sB;
    const float* biasz = BIAS ? bias + (size_t)z * sbias : nullptr;
    float* Cz = C + (size_t)z * sC;

    int tid = threadIdx.x, lane = tid & 31, w = tid >> 5;
    int wm = w & 3, wn = w >> 2;          // 4 x 2 warp grid
    int m0 = blockIdx.x * BM;

    float4 acc[2][NJ];
#pragma unroll
    for (int i = 0; i < 2; i++)
#pragma unroll
        for (int j = 0; j < NJ; j++) acc[i][j] = make_float4(0.f, 0.f, 0.f, 0.f);

    for (int k0 = 0; k0 < K; k0 += BK) {
        fill_A<BM, BK>(As, A, m0, M, K, k0);
        fill_B<BK, BN>(Bs, Bz, k0, ldb);
        __syncthreads();
#pragma unroll
        for (int k8 = 0; k8 < BK / 8; k8++) {
            uint32_t a[2][4], b[NJ][2];
#pragma unroll
            for (int i = 0; i < 2; i++) {
                int tm = wm * 2 + i;
                *(uint4*)a[i] = *(const uint4*)&As[(size_t)((k8 * (BM / 16) + tm) * 32 + lane) * 4];
            }
#pragma unroll
            for (int j = 0; j < NJ; j++) {
                int tn = wn * NJ + j;
                *(uint2*)b[j] = *(const uint2*)&Bs[(size_t)((k8 * (BN / 8) + tn) * 32 + lane) * 2];
            }
#pragma unroll
            for (int i = 0; i < 2; i++)
#pragma unroll
                for (int j = 0; j < NJ; j++) mma_tf32(acc[i][j], a[i], b[j]);
        }
        __syncthreads();
    }

    int g = lane >> 2, tg = lane & 3;
#pragma unroll
    for (int i = 0; i < 2; i++) {
        int r0 = m0 + wm * 32 + i * 16 + g;
#pragma unroll
        for (int j = 0; j < NJ; j++) {
            int c = (wn * NJ + j) * 8 + tg * 2;
            float bx = 0.f, by = 0.f;
            if (BIAS) { float2 bb = *(const float2*)&biasz[c]; bx = bb.x; by = bb.y; }
            float2 v01 = make_float2(acc[i][j].x + bx, acc[i][j].y + by);
            float2 v23 = make_float2(acc[i][j].z + bx, acc[i][j].w + by);
            if (LRELU) {
                v01.x = lrelu(v01.x); v01.y = lrelu(v01.y);
                v23.x = lrelu(v23.x); v23.y = lrelu(v23.y);
            }
            if (r0 < M)     *(float2*)&Cz[(size_t)r0 * ldc + c] = v01;
            if (r0 + 8 < M) *(float2*)&Cz[(size_t)(r0 + 8) * ldc + c] = v23;
        }
    }
}

// ---- batched dual GEMM (unchanged from R4) ----
template <int K>
__global__ __launch_bounds__(256) void dual_gemm_tc_b(
    const float* __restrict__ A1, size_t sA1,
    const float* __restrict__ B1, size_t sB1, const float* __restrict__ b1, size_t sb1,
    const float* __restrict__ A2, size_t sA2,
    const float* __restrict__ B2, size_t sB2, const float* __restrict__ b2, size_t sb2,
    const float* __restrict__ idemb, float* __restrict__ out, size_t sOut, int M) {
    const int BM = 128, BK = 16, BN = 64;
    __shared__ __align__(16) uint32_t As1[(BK / 8) * (BM / 16) * 32 * 4];
    __shared__ __align__(16) uint32_t As2[(BK / 8) * (BM / 16) * 32 * 4];
    __shared__ __align__(16) uint32_t Bs1[(BK / 8) * (BN / 8) * 32 * 2];
    __shared__ __align__(16) uint32_t Bs2[(BK / 8) * (BN / 8) * 32 * 2];
    int z = blockIdx.z;
    const float* A1z = A1 + (size_t)z * sA1;
    const float* A2z = A2 + (size_t)z * sA2;
    const float* B1z = B1 + (size_t)z * sB1;
    const float* B2z = B2 + (size_t)z * sB2;
    const float* b1z = b1 + (size_t)z * sb1;
    const float* b2z = b2 + (size_t)z * sb2;
    float* outz = out + (size_t)z * sOut;

    int tid = threadIdx.x, lane = tid & 31, w = tid >> 5;
    int wm = w >> 1, wn = w & 1;
    int m0 = blockIdx.x * BM;

    float4 acc1[2][4], acc2[2][4];
#pragma unroll
    for (int i = 0; i < 2; i++)
#pragma unroll
        for (int j = 0; j < 4; j++) {
            acc1[i][j] = make_float4(0.f, 0.f, 0.f, 0.f);
            acc2[i][j] = make_float4(0.f, 0.f, 0.f, 0.f);
        }

    for (int k0 = 0; k0 < K; k0 += BK) {
        fill_A<BM, BK>(As1, A1z, m0, M, K, k0);
        fill_A<BM, BK>(As2, A2z, m0, M, K, k0);
        fill_B<BK, BN>(Bs1, B1z, k0, BN);
        fill_B<BK, BN>(Bs2, B2z, k0, BN);
        __syncthreads();
#pragma unroll
        for (int k8 = 0; k8 < BK / 8; k8++) {
            uint32_t a1[2][4], a2[2][4], bf1[4][2], bf2[4][2];
#pragma unroll
            for (int i = 0; i < 2; i++) {
                int tm = wm * 2 + i;
                *(uint4*)a1[i] = *(const uint4*)&As1[(size_t)((k8 * (BM / 16) + tm) * 32 + lane) * 4];
                *(uint4*)a2[i] = *(const uint4*)&As2[(size_t)((k8 * (BM / 16) + tm) * 32 + lane) * 4];
            }
#pragma unroll
            for (int j = 0; j < 4; j++) {
                int tn = wn * 4 + j;
                *(uint2*)bf1[j] = *(const uint2*)&Bs1[(size_t)((k8 * (BN / 8) + tn) * 32 + lane) * 2];
                *(uint2*)bf2[j] = *(const uint2*)&Bs2[(size_t)((k8 * (BN / 8) + tn) * 32 + lane) * 2];
            }
#pragma unroll
            for (int i = 0; i < 2; i++)
#pragma unroll
                for (int j = 0; j < 4; j++) {
                    mma_tf32(acc1[i][j], a1[i], bf1[j]);
                    mma_tf32(acc2[i][j], a2[i], bf2[j]);
                }
        }
        __syncthreads();
    }

    int g = lane >> 2, tg = lane & 3;
#pragma unroll
    for (int i = 0; i < 2; i++) {
        int r0 = m0 + wm * 32 + i * 16 + g;
#pragma unroll
        for (int j = 0; j < 4; j++) {
            int c = wn * 32 + j * 8 + tg * 2;
            float2 bb1 = *(const float2*)&b1z[c];
            float2 bb2 = *(const float2*)&b2z[c];
            if (r0 < M) {
                float2 idv = *(const float2*)&idemb[(size_t)r0 * D_X + c];
                float u1 = lrelu(acc1[i][j].x + bb1.x);
                float u2 = lrelu(acc1[i][j].y + bb1.y);
                float o1 = lrelu(acc2[i][j].x + bb2.x + u1 + idv.x);
                float o2 = lrelu(acc2[i][j].y + bb2.y + u2 + idv.y);
                *(float2*)&outz[(size_t)r0 * D_X + c] = make_float2(o1, o2);
            }
            if (r0 + 8 < M) {
                float2 idv = *(const float2*)&idemb[(size_t)(r0 + 8) * D_X + c];
                float u1 = lrelu(acc1[i][j].z + bb1.x);
                float u2 = lrelu(acc1[i][j].w + bb1.y);
                float o1 = lrelu(acc2[i][j].z + bb2.x + u1 + idv.x);
                float o2 = lrelu(acc2[i][j].w + bb2.y + u2 + idv.y);
                *(float2*)&outz[(size_t)(r0 + 8) * D_X + c] = make_float2(o1, o2);
            }
        }
    }
}

// ---------------- CSR build ----------------
__global__ void zero_int(int* __restrict__ p, int n) {
    int i = blockIdx.x * blockDim.x + threadIdx.x;
    if (i < n) p[i] = 0;
}

__global__ void deg_hist(const int* __restrict__ ei, int E, int* __restrict__ deg) {
    int e = blockIdx.x * blockDim.x + threadIdx.x;
    if (e < E) atomicAdd(&deg[ei[E + e]], 1);
}

__global__ void deg_partials(const int* __restrict__ deg, int* __restrict__ bsum, int n) {
    __shared__ int s[256];
    int i = blockIdx.x * 256 + threadIdx.x;
    s[threadIdx.x] = (i < n) ? deg[i] : 0;
    __syncthreads();
    for (int o = 128; o > 0; o >>= 1) {
        if (threadIdx.x < o) s[threadIdx.x] += s[threadIdx.x + o];
        __syncthreads();
    }
    if (threadIdx.x == 0) bsum[blockIdx.x] = s[0];
}

__global__ void deg_scan(const int* __restrict__ deg, const int* __restrict__ bsum,
                         int* __restrict__ rp, int* __restrict__ cursor, int n) {
    __shared__ int s[256];
    __shared__ int off_s;
    int b = blockIdx.x, t = threadIdx.x;
    if (t == 0) {
        int o = 0;
        for (int k = 0; k < b; k++) o += bsum[k];
        off_s = o;
    }
    int i = b * 256 + t;
    int v = (i < n) ? deg[i] : 0;
    s[t] = v;
    __syncthreads();
    for (int o = 1; o < 256; o <<= 1) {
        int add = (t >= o) ? s[t - o] : 0;
        __syncthreads();
        s[t] += add;
        __syncthreads();
    }
    int ex = s[t] - v + off_s;
    if (i < n) { rp[i] = ex; cursor[i] = ex; }
    if (i == n - 1) rp[n] = ex + v;
}

__global__ void csr_fill(const int* __restrict__ ei, int E,
                         int* __restrict__ cursor, int* __restrict__ col) {
    int e = blockIdx.x * blockDim.x + threadIdx.x;
    if (e >= E) return;
    int s = ei[e], d = ei[E + e];
    int pos = atomicAdd(&cursor[d], 1);
    col[pos] = s;
}

// words row_ptr from sorted item ids
__global__ void words_rp_k(const int* __restrict__ words, int W, int* __restrict__ rp) {
    int w = blockIdx.x * blockDim.x + threadIdx.x;
    if (w >= W) return;
    int it = words[w];
    int prev = (w == 0) ? -1 : words[w - 1];
    for (int t = prev + 1; t <= it; t++) rp[t] = w;
    if (w == W - 1)
        for (int t = it + 1; t <= I_NODES; t++) rp[t] = W;
}

// ---------------- gathers ----------------
__global__ void words_gather(const int* __restrict__ rp, const int* __restrict__ words,
                             int W, const float* __restrict__ word_emb,
                             float* __restrict__ tfeat) {
    int it = (int)(((long)blockIdx.x * blockDim.x + threadIdx.x) >> 5);
    int lane = threadIdx.x & 31;
    if (it >= I_NODES) return;
    int beg = rp[it], end = rp[it + 1];
    float4 a = make_float4(0.f, 0.f, 0.f, 0.f);
    int j = beg;
    for (; j + 4 <= end; j += 4) {
        int w0 = words[W + j], w1 = words[W + j + 1], w2 = words[W + j + 2], w3 = words[W + j + 3];
        acc4(a, ((const float4*)(word_emb + (size_t)w0 * D_LAT))[lane]);
        acc4(a, ((const float4*)(word_emb + (size_t)w1 * D_LAT))[lane]);
        acc4(a, ((const float4*)(word_emb + (size_t)w2 * D_LAT))[lane]);
        acc4(a, ((const float4*)(word_emb + (size_t)w3 * D_LAT))[lane]);
    }
    for (; j < end; j++)
        acc4(a, ((const float4*)(word_emb + (size_t)words[W + j] * D_LAT))[lane]);
    float inv = 1.0f / (float)max(end - beg, 1);
    a.x *= inv; a.y *= inv; a.z *= inv; a.w *= inv;
    ((float4*)(tfeat + (size_t)it * D_LAT))[lane] = a;
}

__global__ void gather128_b(const int* __restrict__ rp, const int* __restrict__ col,
                            const float* __restrict__ xbase, float* __restrict__ aggbase) {
    int n = (int)(((long)blockIdx.x * blockDim.x + threadIdx.x) >> 5);
    int lane = threadIdx.x & 31;
    if (n >= N_NODES) return;
    int z = blockIdx.y;
    const float* x = xbase + (size_t)z * SZ_X;
    float* agg = aggbase + (size_t)z * SZ_X;
    int beg = rp[n], end = rp[n + 1];
    float4 a = make_float4(0.f, 0.f, 0.f, 0.f);
    int j = beg;
    for (; j + 4 <= end; j += 4) {
        int s0 = col[j], s1 = col[j + 1], s2 = col[j + 2], s3 = col[j + 3];
        acc4(a, ((const float4*)(x + (size_t)s0 * D_LAT))[lane]);
        acc4(a, ((const float4*)(x + (size_t)s1 * D_LAT))[lane]);
        acc4(a, ((const float4*)(x + (size_t)s2 * D_LAT))[lane]);
        acc4(a, ((const float4*)(x + (size_t)s3 * D_LAT))[lane]);
    }
    for (; j < end; j++)
        acc4(a, ((const float4*)(x + (size_t)col[j] * D_LAT))[lane]);
    ((float4*)(agg + (size_t)n * D_LAT))[lane] = a;
}

__global__ void gather64_b(const int* __restrict__ rp, const int* __restrict__ col,
                           const float* __restrict__ xbase, float* __restrict__ aggbase) {
    int n = (int)(((long)blockIdx.x * blockDim.x + threadIdx.x) >> 5);
    int lane = threadIdx.x & 31;
    if (n >= N_NODES) return;
    int z = blockIdx.y;
    const float* x = xbase + (size_t)z * SZ_X64;
    float* agg = aggbase + (size_t)z * SZ_X64;
    int beg = rp[n], end = rp[n + 1];
    float2 a = make_float2(0.f, 0.f);
    int j = beg;
    for (; j + 4 <= end; j += 4) {
        int s0 = col[j], s1 = col[j + 1], s2 = col[j + 2], s3 = col[j + 3];
        acc2(a, ((const float2*)(x + (size_t)s0 * D_X))[lane]);
        acc2(a, ((const float2*)(x + (size_t)s1 * D_X))[lane]);
        acc2(a, ((const float2*)(x + (size_t)s2 * D_X))[lane]);
        acc2(a, ((const float2*)(x + (size_t)s3 * D_X))[lane]);
    }
    for (; j < end; j++)
        acc2(a, ((const float2*)(x + (size_t)col[j] * D_X))[lane]);
    ((float2*)(agg + (size_t)n * D_X))[lane] = a;
}

// ---------------- misc ----------------
__global__ void transpose_all(const float* __restrict__ w0, const float* __restrict__ w1,
                              const float* __restrict__ w2, const float* __restrict__ w3,
                              const float* __restrict__ w4,
                              float* __restrict__ o0, float* __restrict__ o1,
                              float* __restrict__ o2, float* __restrict__ o3,
                              float* __restrict__ o4) {
    int i = blockIdx.x * blockDim.x + threadIdx.x;
    const float* in; float* out; int R, C;
    if (i < 49152)       { in = w0; out = o0; R = 128; C = 128; }
    else if (i < 73728)  { i -= 49152;  in = w1; out = o1; R = 64; C = 128; }
    else if (i < 98304)  { i -= 73728;  in = w2; out = o2; R = 64; C = 128; }
    else if (i < 110592) { i -= 98304;  in = w3; out = o3; R = 64; C = 64; }
    else if (i < 122880) { i -= 110592; in = w4; out = o4; R = 64; C = 64; }
    else return;
    int m = i / (R * C);
    int rem = i - m * R * C;
    int r = rem / C;
    int c = rem - r * C;
    out[m * R * C + c * R + r] = in[i];
}

__global__ void normalize_x_b(const float* __restrict__ pref, float* __restrict__ xbase) {
    int row = (int)(((long)blockIdx.x * blockDim.x + threadIdx.x) >> 5);
    int lane = threadIdx.x & 31;
    if (row >= N_NODES) return;
    int z = blockIdx.y;
    float* x = xbase + (size_t)z * SZ_X;
    const float* pref_m = pref + (size_t)z * U_NODES * D_LAT;
    const float* src = (row < U_NODES) ? (pref_m + (size_t)row * D_LAT)
                                       : (x + (size_t)row * D_LAT);
    float4 v = ((const float4*)src)[lane];
    float ss = v.x * v.x + v.y * v.y + v.z * v.z + v.w * v.w;
    ss = warp_sum(ss);
    float s = 1.0f / fmaxf(sqrtf(ss), 1e-12f);
    v.x *= s; v.y *= s; v.z *= s; v.w *= s;
    ((float4*)(x + (size_t)row * D_LAT))[lane] = v;
}

__global__ void final_kernel(const float* __restrict__ rep,
                             const int* __restrict__ users, const int* __restrict__ pos,
                             const int* __restrict__ neg, float* __restrict__ out, int Bn) {
    int gw = (int)(((long)blockIdx.x * blockDim.x + threadIdx.x) >> 5);
    int lane = threadIdx.x & 31;
    if (gw >= Bn) return;
    int u = users[gw], p = pos[gw], n = neg[gw];
    const size_t stride = (size_t)N_NODES * D_X;
    const float* r0 = rep;
    const float* r1 = rep + stride;
    const float* r2 = rep + 2 * stride;

    auto ld = [&](const float* base, int node) {
        return ((const float2*)(base + (size_t)node * D_X))[lane];
    };
    float2 t_u = ld(r2, u), t_p = ld(r2, p), t_n = ld(r2, n);
    float2 a_u = ld(r0, u), b_u = ld(r1, u);
    float2 a_p = ld(r0, p), b_p = ld(r1, p);
    float2 a_n = ld(r0, n), b_n = ld(r1, n);

    const float third = 1.0f / 3.0f;
    float2 pu = make_float2((a_u.x + b_u.x + t_u.x) * third, (a_u.y + b_u.y + t_u.y) * third);
    float2 pp = make_float2((a_p.x + b_p.x + t_p.x) * third, (a_p.y + b_p.y + t_p.y) * third);
    float2 pn = make_float2((a_n.x + b_n.x + t_n.x) * third, (a_n.y + b_n.y + t_n.y) * third);

    float prep  = t_u.x * t_p.x + t_u.y * t_p.y;
    float pren  = t_u.x * t_n.x + t_u.y * t_n.y;
    float postp = pu.x * pp.x + pu.y * pp.y;
    float postn = pu.x * pn.x + pu.y * pn.y;

    prep = warp_sum(prep);
    pren = warp_sum(pren);
    postp = warp_sum(postp);
    postn = warp_sum(postn);

    if (lane == 0) {
        float sp = 1.0f / (1.0f + expf(-prep));
        float sn = 1.0f / (1.0f + expf(-pren));
        out[gw]          = postp * sp;
        out[Bn + gw]     = postn * sn;
        out[2 * Bn + gw] = prep;
        out[3 * Bn + gw] = pren;
    }
}

// ---------------- host orchestration ----------------
static inline int nblk(long n, int t) { return (int)((n + t - 1) / t); }

extern "C" void kernel_launch(void* const* d_in, const int* in_sizes, int n_in,
                              void* d_out, int out_size) {
    const float* v_feat   = (const float*)d_in[0];
    const float* a_feat   = (const float*)d_in[1];
    const float* word_emb = (const float*)d_in[2];
    const float* id_emb   = (const float*)d_in[3];
    const float* pref     = (const float*)d_in[4];
    const float* mlp_w    = (const float*)d_in[5];
    const float* mlp_b    = (const float*)d_in[6];
    const float* conv1_w  = (const float*)d_in[7];
    const float* lin1_w   = (const float*)d_in[8];
    const float* lin1_b   = (const float*)d_in[9];
    const float* g1_w     = (const float*)d_in[10];
    const float* g1_b     = (const float*)d_in[11];
    const float* conv2_w  = (const float*)d_in[12];
    const float* lin2_w   = (const float*)d_in[13];
    const float* lin2_b   = (const float*)d_in[14];
    const float* g2_w     = (const float*)d_in[15];
    const float* g2_b     = (const float*)d_in[16];
    const int*   edges    = (const int*)d_in[17];
    const int*   words    = (const int*)d_in[18];
    const int*   users    = (const int*)d_in[19];
    const int*   posn     = (const int*)d_in[20];
    const int*   negn     = (const int*)d_in[21];

    const int E  = in_sizes[17] / 2;   // 500000 directed edges
    const int W  = in_sizes[18] / 2;   // 600000
    const int Bn = in_sizes[19];       // 2048

    float* sc = nullptr;
    cudaGetSymbolAddress((void**)&sc, g_scratch);

    float* tfeat = sc + OFF_TFEAT;
    float* x     = sc + R_X;                       // stride SZ_X   (layer 1)
    float* rep   = sc + R_X;                       // stride SZ_X64 (dual2 out)
    float* agg   = sc + R_AGG;                     // stride SZ_X
    float* x64   = sc + R_AGG;                     // stride SZ_X64
    float* agg64 = sc + R_AGG + 3 * SZ_X64;        // stride SZ_X64
    float* h     = sc + R_H;                       // stride SZ_X
    float* h64   = sc + R_H;                       // stride SZ_X64

    int* ib     = (int*)(sc + OFF_CSR);
    int* cursor = ib + ICUR;
    int* rp     = ib + IRP;
    int* bsum   = ib + IBSUM;
    int* col    = ib + ICOL;
    int* wrp    = ib + IWRP;

    const int NB = nblk(N_NODES, 256);   // 274

    // ---- CSR build + weight prep ----
    transpose_all<<<nblk(122880, 256), 256>>>(mlp_w, lin1_w, g1_w, lin2_w, g2_w,
                                              sc + OFF_MLPT, sc + OFF_LIN1T, sc + OFF_G1T,
                                              sc + OFF_LIN2T, sc + OFF_G2T);
    zero_int<<<nblk(N_NODES + 1, 256), 256>>>(cursor, N_NODES + 1);
    deg_hist<<<nblk(E, 256), 256>>>(edges, E, cursor);
    deg_partials<<<NB, 256>>>(cursor, bsum, N_NODES);
    deg_scan<<<NB, 256>>>(cursor, bsum, rp, cursor, N_NODES);
    csr_fill<<<nblk(E, 256), 256>>>(edges, E, cursor, col);
    words_rp_k<<<nblk(W, 256), 256>>>(words, W, wrp);

    // ---- t_feat gather-mean ----
    words_gather<<<nblk((long)I_NODES * 32, 256), 256>>>(wrp, words, W, word_emb, tfeat);

    // ---- mlp GEMM (BN=128, A read once) -> x rows [U, N) ----
    {
        dim3 grid(nblk(I_NODES, 128), 1, 3);
        gemm_tc_b<128, 128, true, false><<<grid, 256>>>(
            v_feat, a_feat, tfeat,
            sc + OFF_MLPT, 128 * 128, mlp_b, 128,
            x + (size_t)U_NODES * D_LAT, SZ_X, I_NODES, 128, 128);
    }
    // ---- normalize ----
    {
        dim3 grid(nblk((long)N_NODES * 32, 256), 3);
        normalize_x_b<<<grid, 256>>>(pref, x);
    }
    // ---- layer-1 gather (no zero, no atomics) ----
    {
        dim3 grid(nblk((long)N_NODES * 32, 256), 3);
        gather128_b<<<grid, 256>>>(rp, col, x, agg);
    }
    // ---- conv1 (BN=128) ----
    {
        dim3 grid(nblk(N_NODES, 128), 1, 3);
        gemm_tc_b<128, 128, false, true><<<grid, 256>>>(
            agg, agg + SZ_X, agg + 2 * SZ_X,
            conv1_w, 128 * 128, nullptr, 0,
            h, SZ_X, N_NODES, 128, 128);
    }
    // ---- dual1: x64 = lrelu(h@g1.T + g1b + lrelu(x@l1.T + l1b) + id) ----
    {
        dim3 grid(nblk(N_NODES, 128), 1, 3);
        dual_gemm_tc_b<128><<<grid, 256>>>(
            x, SZ_X, sc + OFF_LIN1T, 128 * 64, lin1_b, 64,
            h, SZ_X, sc + OFF_G1T, 128 * 64, g1_b, 64,
            id_emb, x64, SZ_X64, N_NODES);
    }
    // ---- layer-2 gather ----
    {
        dim3 grid(nblk((long)N_NODES * 32, 256), 3);
        gather64_b<<<grid, 256>>>(rp, col, x64, agg64);
    }
    // ---- conv2 (BN=64) ----
    {
        dim3 grid(nblk(N_NODES, 128), 1, 3);
        gemm_tc_b<64, 64, false, true><<<grid, 256>>>(
            agg64, agg64 + SZ_X64, agg64 + 2 * SZ_X64,
            conv2_w, 64 * 64, nullptr, 0,
            h64, SZ_X64, N_NODES, 64, 64);
    }
    // ---- dual2 -> rep ----
    {
        dim3 grid(nblk(N_NODES, 128), 1, 3);
        dual_gemm_tc_b<64><<<grid, 256>>>(
            x64, SZ_X64, sc + OFF_LIN2T, 64 * 64, lin2_b, 64,
            h64, SZ_X64, sc + OFF_G2T, 64 * 64, g2_b, 64,
            id_emb, rep, SZ_X64, N_NODES);
    }
    // ---- final scoring ----
    final_kernel<<<nblk((long)Bn * 32, 256), 256>>>(rep, users, posn, negn,
                                                    (float*)d_out, Bn);
}